// round 3
// baseline (speedup 1.0000x reference)
#include <cuda_runtime.h>
#include <math.h>
#include <stdint.h>

#define NN 50000
#define EE 800000
#define CC 64

// ---------------- scratch ----------------
__device__ float    g_m[NN * CC];
__device__ float    g_cnt[NN];
__device__ float    g_s1[NN * CC];
__device__ float    g_s2[NN * CC];
__device__ unsigned g_mn[NN * CC];
__device__ unsigned g_mx[NN * CC];
__device__ float    g_agg[NN * 4 * CC];
__device__ float    g_a[NN];
__device__ float    g_ia[NN];
__device__ float    g_out_node[NN * CC];
__device__ float    g_gi[NN * 3 * CC];
__device__ float    g_gh[NN * 3 * CC];
__device__ float    g_avgsum[1];

__device__ __forceinline__ unsigned f2o(float f) {
    unsigned u = __float_as_uint(f);
    return (u & 0x80000000u) ? ~u : (u | 0x80000000u);
}
__device__ __forceinline__ float o2f(unsigned u) {
    return (u & 0x80000000u) ? __uint_as_float(u ^ 0x80000000u) : __uint_as_float(~u);
}

// ---------------- packed f32x2 helpers (sm_10x FFMA2) ----------------
__device__ __forceinline__ unsigned long long pack2(float lo, float hi) {
    unsigned long long r;
    asm("mov.b64 %0, {%1, %2};" : "=l"(r) : "f"(lo), "f"(hi));
    return r;
}
__device__ __forceinline__ void unpack2(unsigned long long v, float& lo, float& hi) {
    asm("mov.b64 {%0, %1}, %2;" : "=f"(lo), "=f"(hi) : "l"(v));
}
__device__ __forceinline__ void fma2(unsigned long long& d, unsigned long long a,
                                     unsigned long long b) {
    asm("fma.rn.f32x2 %0, %1, %2, %0;" : "+l"(d) : "l"(a), "l"(b));
}

// 8x8 micro-step: acc[8][4] (j packed in pairs), A k-slice (128 wide), B k-slice (64 wide)
__device__ __forceinline__ void micro_fma(unsigned long long acc[8][4],
                                          const float* __restrict__ As_k,
                                          const float* __restrict__ Bs_k,
                                          int tr, int tc) {
    float4 a_lo = *reinterpret_cast<const float4*>(As_k + tr * 8);
    float4 a_hi = *reinterpret_cast<const float4*>(As_k + tr * 8 + 4);
    float4 b_lo = *reinterpret_cast<const float4*>(Bs_k + tc * 8);
    float4 b_hi = *reinterpret_cast<const float4*>(Bs_k + tc * 8 + 4);
    unsigned long long bb0 = pack2(b_lo.x, b_lo.y);
    unsigned long long bb1 = pack2(b_lo.z, b_lo.w);
    unsigned long long bb2 = pack2(b_hi.x, b_hi.y);
    unsigned long long bb3 = pack2(b_hi.z, b_hi.w);
    float av[8] = {a_lo.x, a_lo.y, a_lo.z, a_lo.w, a_hi.x, a_hi.y, a_hi.z, a_hi.w};
    #pragma unroll
    for (int i = 0; i < 8; i++) {
        unsigned long long aa = pack2(av[i], av[i]);
        fma2(acc[i][0], aa, bb0);
        fma2(acc[i][1], aa, bb1);
        fma2(acc[i][2], aa, bb2);
        fma2(acc[i][3], aa, bb3);
    }
}

// ---------------- init ----------------
__global__ void init_kernel(int N) {
    int idx = blockIdx.x * 256 + threadIdx.x;
    int total = N * CC;
    if (idx < total) {
        g_s1[idx] = 0.f;
        g_s2[idx] = 0.f;
        g_mn[idx] = 0xFFFFFFFFu;
        g_mx[idx] = 0u;
    }
    if (idx < N) g_cnt[idx] = 0.f;
    if (idx == 0) g_avgsum[0] = 0.f;
}

// ---------------- avg_log ----------------
__global__ void avglog_kernel(const float* __restrict__ deg_hist, int N) {
    int idx = blockIdx.x * 256 + threadIdx.x;
    float v = (idx < N) ? logf(deg_hist[idx] + 1.f) : 0.f;
    #pragma unroll
    for (int o = 16; o; o >>= 1) v += __shfl_down_sync(0xFFFFFFFFu, v, o);
    __shared__ float sred[8];
    if ((threadIdx.x & 31) == 0) sred[threadIdx.x >> 5] = v;
    __syncthreads();
    if (threadIdx.x < 8) {
        v = sred[threadIdx.x];
        #pragma unroll
        for (int o = 4; o; o >>= 1) v += __shfl_down_sync(0xFFu, v, o);
        if (threadIdx.x == 0) atomicAdd(&g_avgsum[0], v);
    }
}

// ---------------- SGEMM: BM=128, BN=64, BK=16, 128 threads, 8x8, FFMA2 ----------------
__global__ void __launch_bounds__(128) gemm128(const float* __restrict__ A,
                                               const float* __restrict__ B,
                                               const float* __restrict__ bias,
                                               float* __restrict__ Cout,
                                               int M, int Ncol, int K) {
    __shared__ float As[16][128];
    __shared__ float Bs[16][64];
    int tid = threadIdx.x;
    int tr = tid / 8, tc = tid % 8;
    int mBase = blockIdx.y * 128;
    int nBase = blockIdx.x * 64;
    unsigned long long acc[8][4];
    #pragma unroll
    for (int i = 0; i < 8; i++)
        #pragma unroll
        for (int j = 0; j < 4; j++) acc[i][j] = 0ull;

    int brow = tid / 8;             // B stage: row 0..15
    int bcol = (tid % 8) * 8;       // col offset (two float4)

    for (int k0 = 0; k0 < K; k0 += 16) {
        int m = mBase + tid;
        #pragma unroll
        for (int q = 0; q < 4; q++) {
            float4 av = make_float4(0.f, 0.f, 0.f, 0.f);
            if (m < M) av = *reinterpret_cast<const float4*>(&A[(size_t)m * K + k0 + q * 4]);
            As[q * 4 + 0][tid] = av.x;
            As[q * 4 + 1][tid] = av.y;
            As[q * 4 + 2][tid] = av.z;
            As[q * 4 + 3][tid] = av.w;
        }
        *reinterpret_cast<float4*>(&Bs[brow][bcol]) =
            *reinterpret_cast<const float4*>(&B[(size_t)(k0 + brow) * Ncol + nBase + bcol]);
        *reinterpret_cast<float4*>(&Bs[brow][bcol + 4]) =
            *reinterpret_cast<const float4*>(&B[(size_t)(k0 + brow) * Ncol + nBase + bcol + 4]);
        __syncthreads();
        #pragma unroll
        for (int k = 0; k < 16; k++) micro_fma(acc, &As[k][0], &Bs[k][0], tr, tc);
        __syncthreads();
    }

    float bs[8] = {0, 0, 0, 0, 0, 0, 0, 0};
    if (bias) {
        float4 t0 = *reinterpret_cast<const float4*>(&bias[nBase + tc * 8]);
        float4 t1 = *reinterpret_cast<const float4*>(&bias[nBase + tc * 8 + 4]);
        bs[0] = t0.x; bs[1] = t0.y; bs[2] = t0.z; bs[3] = t0.w;
        bs[4] = t1.x; bs[5] = t1.y; bs[6] = t1.z; bs[7] = t1.w;
    }
    #pragma unroll
    for (int i = 0; i < 8; i++) {
        int m = mBase + tr * 8 + i;
        if (m < M) {
            float v[8];
            #pragma unroll
            for (int j = 0; j < 4; j++) unpack2(acc[i][j], v[2 * j], v[2 * j + 1]);
            float4 o0 = make_float4(v[0] + bs[0], v[1] + bs[1], v[2] + bs[2], v[3] + bs[3]);
            float4 o1 = make_float4(v[4] + bs[4], v[5] + bs[5], v[6] + bs[6], v[7] + bs[7]);
            float* cp = &Cout[(size_t)m * Ncol + nBase + tc * 8];
            *reinterpret_cast<float4*>(cp) = o0;
            *reinterpret_cast<float4*>(cp + 4) = o1;
        }
    }
}

// ---------------- edge kernel: 128 edges/block, fused MLP + atomic reduce ----------------
__global__ void __launch_bounds__(128) edge_kernel(const float* __restrict__ edge_attr,
                                                   const int* __restrict__ edge_index,
                                                   const float* __restrict__ Wpre,
                                                   const float* __restrict__ We,
                                                   const float* __restrict__ be,
                                                   const float* __restrict__ bpre,
                                                   int E) {
    __shared__ float sIn[32][128];
    __shared__ float sW[32][64];
    __shared__ int   s_src[128], s_dst[128];
    __shared__ float s_ew[128];
    __shared__ float s_attr[128][3];
    __shared__ float sWe[3][64];
    __shared__ float sbe[64];
    __shared__ float sbpre[64];

    int tid = threadIdx.x;
    int eBase = blockIdx.x * 128;
    int ne = E - eBase; if (ne > 128) ne = 128;

    {
        bool v = tid < ne;
        int e = eBase + (v ? tid : 0);
        s_src[tid] = edge_index[e];
        s_dst[tid] = edge_index[E + e];
        float4 a4 = *reinterpret_cast<const float4*>(&edge_attr[(size_t)e * 4]);
        s_attr[tid][0] = a4.x; s_attr[tid][1] = a4.y; s_attr[tid][2] = a4.z;
        s_ew[tid] = v ? a4.w : 0.f;
        if (tid < 64) {
            sbe[tid] = be[tid];
            sbpre[tid] = bpre[tid];
            sWe[0][tid] = We[tid];
            sWe[1][tid] = We[64 + tid];
            sWe[2][tid] = We[128 + tid];
        }
    }
    __syncthreads();
    if (tid < ne) atomicAdd(&g_cnt[s_dst[tid]], 1.0f);

    int tr = tid / 8, tc = tid % 8;
    unsigned long long acc[8][4];
    #pragma unroll
    for (int i = 0; i < 8; i++)
        #pragma unroll
        for (int j = 0; j < 4; j++) acc[i][j] = 0ull;

    int wrow = tid / 4;           // sW staging: row 0..31
    int wcol = (tid % 4) * 16;    // 16 floats

    #pragma unroll 1
    for (int sp = 0; sp < 6; sp++) {
        int seg = sp >> 1;        // 0:xi(dst) 1:xj(src) 2:ea
        int half = sp & 1;        // 0/1 -> k offset 0/32 in segment
        // stage Wpre rows [seg*64 + half*32, +32)
        #pragma unroll
        for (int q = 0; q < 4; q++) {
            *reinterpret_cast<float4*>(&sW[wrow][wcol + q * 4]) =
                *reinterpret_cast<const float4*>(
                    &Wpre[(size_t)(seg * 64 + half * 32 + wrow) * 64 + wcol + q * 4]);
        }
        // build input k-slice for this thread's edge
        {
            float ew = s_ew[tid];
            if (seg < 2) {
                int node = (seg == 0) ? s_dst[tid] : s_src[tid];
                const float4* mp =
                    reinterpret_cast<const float4*>(&g_m[(size_t)node * 64 + half * 32]);
                #pragma unroll
                for (int f = 0; f < 8; f++) {
                    float4 v = mp[f];
                    sIn[f * 4 + 0][tid] = ew * v.x;
                    sIn[f * 4 + 1][tid] = ew * v.y;
                    sIn[f * 4 + 2][tid] = ew * v.z;
                    sIn[f * 4 + 3][tid] = ew * v.w;
                }
            } else {
                float a0 = s_attr[tid][0], a1 = s_attr[tid][1], a2 = s_attr[tid][2];
                #pragma unroll
                for (int f = 0; f < 8; f++) {
                    int k = half * 32 + f * 4;
                    float4 w0 = *reinterpret_cast<const float4*>(&sWe[0][k]);
                    float4 w1 = *reinterpret_cast<const float4*>(&sWe[1][k]);
                    float4 w2 = *reinterpret_cast<const float4*>(&sWe[2][k]);
                    float4 bb = *reinterpret_cast<const float4*>(&sbe[k]);
                    sIn[f * 4 + 0][tid] = ew * (a0 * w0.x + a1 * w1.x + a2 * w2.x + bb.x);
                    sIn[f * 4 + 1][tid] = ew * (a0 * w0.y + a1 * w1.y + a2 * w2.y + bb.y);
                    sIn[f * 4 + 2][tid] = ew * (a0 * w0.z + a1 * w1.z + a2 * w2.z + bb.z);
                    sIn[f * 4 + 3][tid] = ew * (a0 * w0.w + a1 * w1.w + a2 * w2.w + bb.w);
                }
            }
        }
        __syncthreads();
        #pragma unroll
        for (int k = 0; k < 32; k++) micro_fma(acc, &sIn[k][0], &sW[k][0], tr, tc);
        __syncthreads();
    }

    // epilogue: atomic segment reductions keyed by dst
    #pragma unroll
    for (int i = 0; i < 8; i++) {
        int e = tr * 8 + i;
        if (e < ne) {
            int d = s_dst[e];
            size_t base = (size_t)d * 64 + tc * 8;
            float v[8];
            #pragma unroll
            for (int j = 0; j < 4; j++) unpack2(acc[i][j], v[2 * j], v[2 * j + 1]);
            #pragma unroll
            for (int j = 0; j < 8; j++) {
                float h = v[j] + sbpre[tc * 8 + j];
                atomicAdd(&g_s1[base + j], h);
                atomicAdd(&g_s2[base + j], h * h);
                unsigned o = f2o(h);
                atomicMin(&g_mn[base + j], o);
                atomicMax(&g_mx[base + j], o);
            }
        }
    }
}

// ---------------- per-node aggregate finalize ----------------
__global__ void node_kernel(int N) {
    int idx = blockIdx.x * 256 + threadIdx.x;
    if (idx >= N * CC) return;
    int n = idx >> 6, c = idx & 63;
    float cnt = g_cnt[n];
    float safe = fmaxf(cnt, 1.f);
    float inv = 1.f / safe;
    float mean = g_s1[idx] * inv;
    float msq  = g_s2[idx] * inv;
    float var  = msq - mean * mean;
    float stdv = sqrtf(fmaxf(var, 0.f) + 1e-5f);
    float mnf = 0.f, mxf = 0.f;
    if (cnt > 0.f) { mnf = o2f(g_mn[idx]); mxf = o2f(g_mx[idx]); }
    size_t b = (size_t)n * 256;
    g_agg[b + c]       = mean;
    g_agg[b + 64 + c]  = mnf;
    g_agg[b + 128 + c] = mxf;
    g_agg[b + 192 + c] = stdv;
    if (c == 0) {
        float avg = g_avgsum[0] / (float)N;
        float logd = logf(safe + 1.f);
        float a = logd / avg;
        g_a[n]  = a;
        g_ia[n] = a * (avg / logd);   // o3 scale: (logd/avg)*(avg/logd), fp-composed
    }
}

// ---------------- Wpost GEMM (K=832) with on-the-fly z construction ----------------
__global__ void __launch_bounds__(128) gemm_post(const float* __restrict__ Wpost,
                                                 const float* __restrict__ bpost, int M) {
    __shared__ float As[16][128];
    __shared__ float Bs[16][64];
    int tid = threadIdx.x;
    int tr = tid / 8, tc = tid % 8;
    int mBase = blockIdx.x * 128;
    unsigned long long acc[8][4];
    #pragma unroll
    for (int i = 0; i < 8; i++)
        #pragma unroll
        for (int j = 0; j < 4; j++) acc[i][j] = 0ull;

    int brow = tid / 8;
    int bcol = (tid % 8) * 8;
    int m = mBase + tid;
    float sa = 0.f, sia = 0.f;
    if (m < M) { sa = g_a[m]; sia = g_ia[m]; }

    for (int k0 = 0; k0 < 832; k0 += 16) {
        #pragma unroll
        for (int q = 0; q < 4; q++) {
            float4 av = make_float4(0.f, 0.f, 0.f, 0.f);
            if (m < M) {
                int k = k0 + q * 4;
                float sc = 1.f;
                const float* src;
                if (k < 64)       src = &g_m[(size_t)m * 64 + k];
                else if (k < 320) src = &g_agg[(size_t)m * 256 + (k - 64)];
                else if (k < 576) { src = &g_agg[(size_t)m * 256 + (k - 320)]; sc = sa; }
                else              { src = &g_agg[(size_t)m * 256 + (k - 576)]; sc = sia; }
                av = *reinterpret_cast<const float4*>(src);
                av.x *= sc; av.y *= sc; av.z *= sc; av.w *= sc;
            }
            As[q * 4 + 0][tid] = av.x;
            As[q * 4 + 1][tid] = av.y;
            As[q * 4 + 2][tid] = av.z;
            As[q * 4 + 3][tid] = av.w;
        }
        *reinterpret_cast<float4*>(&Bs[brow][bcol]) =
            *reinterpret_cast<const float4*>(&Wpost[(size_t)(k0 + brow) * 64 + bcol]);
        *reinterpret_cast<float4*>(&Bs[brow][bcol + 4]) =
            *reinterpret_cast<const float4*>(&Wpost[(size_t)(k0 + brow) * 64 + bcol + 4]);
        __syncthreads();
        #pragma unroll
        for (int k = 0; k < 16; k++) micro_fma(acc, &As[k][0], &Bs[k][0], tr, tc);
        __syncthreads();
    }

    float4 t0 = *reinterpret_cast<const float4*>(&bpost[tc * 8]);
    float4 t1 = *reinterpret_cast<const float4*>(&bpost[tc * 8 + 4]);
    float bs[8] = {t0.x, t0.y, t0.z, t0.w, t1.x, t1.y, t1.z, t1.w};
    #pragma unroll
    for (int i = 0; i < 8; i++) {
        int mm = mBase + tr * 8 + i;
        if (mm < M) {
            float v[8];
            #pragma unroll
            for (int j = 0; j < 4; j++) unpack2(acc[i][j], v[2 * j], v[2 * j + 1]);
            float4 o0 = make_float4(v[0] + bs[0], v[1] + bs[1], v[2] + bs[2], v[3] + bs[3]);
            float4 o1 = make_float4(v[4] + bs[4], v[5] + bs[5], v[6] + bs[6], v[7] + bs[7]);
            float* cp = &g_out_node[(size_t)mm * 64 + tc * 8];
            *reinterpret_cast<float4*>(cp) = o0;
            *reinterpret_cast<float4*>(cp + 4) = o1;
        }
    }
}

// ---------------- GRU elementwise ----------------
__global__ void gru_kernel(const float* __restrict__ x, float* __restrict__ out, int N) {
    int idx = blockIdx.x * 256 + threadIdx.x;
    if (idx >= N * CC) return;
    int n = idx >> 6, c = idx & 63;
    size_t b = (size_t)n * 192;
    float ir = g_gi[b + c],        hr = g_gh[b + c];
    float iz = g_gi[b + 64 + c],   hz = g_gh[b + 64 + c];
    float in_ = g_gi[b + 128 + c], hn = g_gh[b + 128 + c];
    float r = 1.f / (1.f + expf(-(ir + hr)));
    float z = 1.f / (1.f + expf(-(iz + hz)));
    float nn = tanhf(in_ + r * hn);
    out[idx] = (1.f - z) * nn + z * x[idx];
}

// ---------------- launch ----------------
extern "C" void kernel_launch(void* const* d_in, const int* in_sizes, int n_in,
                              void* d_out, int out_size) {
    const float* x         = (const float*)d_in[0];
    const float* edge_attr = (const float*)d_in[1];
    const float* deg_hist  = (const float*)d_in[2];
    const float* W         = (const float*)d_in[3];
    const float* We        = (const float*)d_in[4];
    const float* be        = (const float*)d_in[5];
    const float* Wpre      = (const float*)d_in[6];
    const float* bpre      = (const float*)d_in[7];
    const float* Wpost     = (const float*)d_in[8];
    const float* bpost     = (const float*)d_in[9];
    const float* Wih       = (const float*)d_in[10];
    const float* bih       = (const float*)d_in[11];
    const float* Whh       = (const float*)d_in[12];
    const float* bhh       = (const float*)d_in[13];
    const int*   edge_index = (const int*)d_in[14];

    int N = in_sizes[0] / CC;
    int E = in_sizes[14] / 2;

    float *pm, *pon, *pgi, *pgh;
    cudaGetSymbolAddress((void**)&pm,  g_m);
    cudaGetSymbolAddress((void**)&pon, g_out_node);
    cudaGetSymbolAddress((void**)&pgi, g_gi);
    cudaGetSymbolAddress((void**)&pgh, g_gh);

    int nodeElems = N * CC;
    int mBlocks = (N + 127) / 128;
    init_kernel<<<(nodeElems + 255) / 256, 256>>>(N);
    avglog_kernel<<<(N + 255) / 256, 256>>>(deg_hist, N);
    gemm128<<<dim3(1, mBlocks), 128>>>(x, W, nullptr, pm, N, 64, 64);
    edge_kernel<<<(E + 127) / 128, 128>>>(edge_attr, edge_index, Wpre, We, be, bpre, E);
    node_kernel<<<(nodeElems + 255) / 256, 256>>>(N);
    gemm_post<<<mBlocks, 128>>>(Wpost, bpost, N);
    gemm128<<<dim3(3, mBlocks), 128>>>(pon, Wih, bih, pgi, N, 192, 64);
    gemm128<<<dim3(3, mBlocks), 128>>>(x, Whh, bhh, pgh, N, 192, 64);
    gru_kernel<<<(nodeElems + 255) / 256, 256>>>(x, (float*)d_out, N);
}

// round 4
// speedup vs baseline: 1.3315x; 1.3315x over previous
#include <cuda_runtime.h>
#include <math.h>
#include <stdint.h>

#define NN 50000
#define EE 800000
#define CC 64

typedef unsigned long long ull;

// ---------------- scratch ----------------
__device__ float    g_m[NN * CC];
__device__ float    g_cnt[NN];
__device__ float    g_s1[NN * CC];
__device__ float    g_s2[NN * CC];
__device__ unsigned g_mn[NN * CC];
__device__ unsigned g_mx[NN * CC];
__device__ float    g_agg[NN * 4 * CC];
__device__ float    g_a[NN];
__device__ float    g_ia[NN];
__device__ float    g_out_node[NN * CC];
__device__ float    g_gi[NN * 3 * CC];
__device__ float    g_gh[NN * 3 * CC];
__device__ float    g_avgsum[1];

__device__ __forceinline__ unsigned f2o(float f) {
    unsigned u = __float_as_uint(f);
    return (u & 0x80000000u) ? ~u : (u | 0x80000000u);
}
__device__ __forceinline__ float o2f(unsigned u) {
    return (u & 0x80000000u) ? __uint_as_float(u ^ 0x80000000u) : __uint_as_float(~u);
}

// ---------------- packed f32x2 helpers ----------------
__device__ __forceinline__ ull pack2(float lo, float hi) {
    ull r;
    asm("mov.b64 %0, {%1, %2};" : "=l"(r) : "f"(lo), "f"(hi));
    return r;
}
__device__ __forceinline__ void unpack2(ull v, float& lo, float& hi) {
    asm("mov.b64 {%0, %1}, %2;" : "=f"(lo), "=f"(hi) : "l"(v));
}
__device__ __forceinline__ void fma2(ull& d, ull a, ull b) {
    asm("fma.rn.f32x2 %0, %1, %2, %0;" : "+l"(d) : "l"(a), "l"(b));
}

// 8(m)x4(n) micro-step with FFMA2 packed along m.
// acc[p][j]: p = m-pair (2 adjacent rows), j = n column.
// As_k: row-major k-slice, 8 consecutive floats at tr*8 = 4 packed pairs (free).
// Bs_k: 4 floats at tc*4, duplicated into pairs (4 movs).
__device__ __forceinline__ void micro8x4(ull acc[4][4],
                                         const float* __restrict__ As_k,
                                         const float* __restrict__ Bs_k,
                                         int tr, int tc) {
    float4 a0 = *reinterpret_cast<const float4*>(As_k + tr * 8);
    float4 a1 = *reinterpret_cast<const float4*>(As_k + tr * 8 + 4);
    ull ap[4] = {pack2(a0.x, a0.y), pack2(a0.z, a0.w),
                 pack2(a1.x, a1.y), pack2(a1.z, a1.w)};
    float4 b = *reinterpret_cast<const float4*>(Bs_k + tc * 4);
    ull bb[4] = {pack2(b.x, b.x), pack2(b.y, b.y), pack2(b.z, b.z), pack2(b.w, b.w)};
    #pragma unroll
    for (int p = 0; p < 4; p++)
        #pragma unroll
        for (int j = 0; j < 4; j++) fma2(acc[p][j], ap[p], bb[j]);
}

// ---------------- init ----------------
__global__ void init_kernel(int N) {
    int idx = blockIdx.x * 256 + threadIdx.x;
    int total = N * CC;
    if (idx < total) {
        g_s1[idx] = 0.f;
        g_s2[idx] = 0.f;
        g_mn[idx] = 0xFFFFFFFFu;
        g_mx[idx] = 0u;
    }
    if (idx < N) g_cnt[idx] = 0.f;
    if (idx == 0) g_avgsum[0] = 0.f;
}

// ---------------- avg_log ----------------
__global__ void avglog_kernel(const float* __restrict__ deg_hist, int N) {
    int idx = blockIdx.x * 256 + threadIdx.x;
    float v = (idx < N) ? logf(deg_hist[idx] + 1.f) : 0.f;
    #pragma unroll
    for (int o = 16; o; o >>= 1) v += __shfl_down_sync(0xFFFFFFFFu, v, o);
    __shared__ float sred[8];
    if ((threadIdx.x & 31) == 0) sred[threadIdx.x >> 5] = v;
    __syncthreads();
    if (threadIdx.x < 8) {
        v = sred[threadIdx.x];
        #pragma unroll
        for (int o = 4; o; o >>= 1) v += __shfl_down_sync(0xFFu, v, o);
        if (threadIdx.x == 0) atomicAdd(&g_avgsum[0], v);
    }
}

// ---------------- SGEMM: BM=128, BN=64, BK=16, 256 threads, 8x4 FFMA2 ----------------
__global__ void __launch_bounds__(256) gemm256(const float* __restrict__ A,
                                               const float* __restrict__ B,
                                               const float* __restrict__ bias,
                                               float* __restrict__ Cout,
                                               int M, int Ncol, int K) {
    __shared__ float As[16][128];
    __shared__ float Bs[16][64];
    int tid = threadIdx.x;
    int tr = tid / 16, tc = tid % 16;
    int mBase = blockIdx.y * 128;
    int nBase = blockIdx.x * 64;
    ull acc[4][4];
    #pragma unroll
    for (int p = 0; p < 4; p++)
        #pragma unroll
        for (int j = 0; j < 4; j++) acc[p][j] = 0ull;

    int ar = tid & 127;            // A stage row
    int ak = (tid >> 7) * 8;       // A stage k offset (0 or 8)
    int brow = tid / 16;           // B stage row 0..15
    int bcol = (tid % 16) * 4;

    for (int k0 = 0; k0 < K; k0 += 16) {
        int m = mBase + ar;
        float4 a0 = make_float4(0.f, 0.f, 0.f, 0.f), a1 = a0;
        if (m < M) {
            const float* ap = &A[(size_t)m * K + k0 + ak];
            a0 = *reinterpret_cast<const float4*>(ap);
            a1 = *reinterpret_cast<const float4*>(ap + 4);
        }
        As[ak + 0][ar] = a0.x; As[ak + 1][ar] = a0.y;
        As[ak + 2][ar] = a0.z; As[ak + 3][ar] = a0.w;
        As[ak + 4][ar] = a1.x; As[ak + 5][ar] = a1.y;
        As[ak + 6][ar] = a1.z; As[ak + 7][ar] = a1.w;
        *reinterpret_cast<float4*>(&Bs[brow][bcol]) =
            *reinterpret_cast<const float4*>(&B[(size_t)(k0 + brow) * Ncol + nBase + bcol]);
        __syncthreads();
        #pragma unroll
        for (int k = 0; k < 16; k++) micro8x4(acc, &As[k][0], &Bs[k][0], tr, tc);
        __syncthreads();
    }

    float bs[4] = {0.f, 0.f, 0.f, 0.f};
    if (bias) {
        float4 t = *reinterpret_cast<const float4*>(&bias[nBase + tc * 4]);
        bs[0] = t.x; bs[1] = t.y; bs[2] = t.z; bs[3] = t.w;
    }
    #pragma unroll
    for (int p = 0; p < 4; p++) {
        float v0[4], v1[4];
        #pragma unroll
        for (int j = 0; j < 4; j++) unpack2(acc[p][j], v0[j], v1[j]);
        int m0 = mBase + tr * 8 + 2 * p;
        if (m0 < M) {
            float4 o = make_float4(v0[0] + bs[0], v0[1] + bs[1], v0[2] + bs[2], v0[3] + bs[3]);
            *reinterpret_cast<float4*>(&Cout[(size_t)m0 * Ncol + nBase + tc * 4]) = o;
        }
        if (m0 + 1 < M) {
            float4 o = make_float4(v1[0] + bs[0], v1[1] + bs[1], v1[2] + bs[2], v1[3] + bs[3]);
            *reinterpret_cast<float4*>(&Cout[(size_t)(m0 + 1) * Ncol + nBase + tc * 4]) = o;
        }
    }
}

// ---------------- edge kernel: 128 edges/block, 256 threads, fused MLP + atomics ----------------
__global__ void __launch_bounds__(256) edge_kernel(const float* __restrict__ edge_attr,
                                                   const int* __restrict__ edge_index,
                                                   const float* __restrict__ Wpre,
                                                   const float* __restrict__ We,
                                                   const float* __restrict__ be,
                                                   const float* __restrict__ bpre,
                                                   int E) {
    __shared__ float sIn[32][128];   // [k][edge]
    __shared__ float sW[32][64];     // [k][channel]
    __shared__ int   s_src[128], s_dst[128];
    __shared__ float s_ew[128];
    __shared__ float s_attr[128][3];
    __shared__ float sWe[3][64];
    __shared__ float sbe[64];
    __shared__ float sbpre[64];

    int tid = threadIdx.x;
    int eBase = blockIdx.x * 128;
    int ne = E - eBase; if (ne > 128) ne = 128;

    if (tid < 128) {
        bool v = tid < ne;
        int e = eBase + (v ? tid : 0);
        s_src[tid] = edge_index[e];
        s_dst[tid] = edge_index[E + e];
        float4 a4 = *reinterpret_cast<const float4*>(&edge_attr[(size_t)e * 4]);
        s_attr[tid][0] = a4.x; s_attr[tid][1] = a4.y; s_attr[tid][2] = a4.z;
        s_ew[tid] = v ? a4.w : 0.f;
    } else {
        int t = tid - 128;
        if (t < 64) {
            sbe[t] = be[t];
            sbpre[t] = bpre[t];
            sWe[0][t] = We[t];
            sWe[1][t] = We[64 + t];
            sWe[2][t] = We[128 + t];
        }
    }
    __syncthreads();
    if (tid < ne) atomicAdd(&g_cnt[s_dst[tid]], 1.0f);

    int tr = tid / 16, tc = tid % 16;
    ull acc[4][4];
    #pragma unroll
    for (int p = 0; p < 4; p++)
        #pragma unroll
        for (int j = 0; j < 4; j++) acc[p][j] = 0ull;

    int le  = tid & 127;     // edge this thread stages
    int h16 = tid >> 7;      // which 16-k half this thread stages (0/1)
    int wrow = tid / 8;      // sW staging: row 0..31
    int wcol = (tid % 8) * 8;

    #pragma unroll 1
    for (int sp = 0; sp < 6; sp++) {
        int seg = sp >> 1;    // 0:xi(dst) 1:xj(src) 2:ea
        int half = sp & 1;    // k offset 0/32 within segment
        // stage Wpre rows [seg*64 + half*32, +32)
        {
            const float* wp = &Wpre[(size_t)(seg * 64 + half * 32 + wrow) * 64 + wcol];
            *reinterpret_cast<float4*>(&sW[wrow][wcol]) =
                *reinterpret_cast<const float4*>(wp);
            *reinterpret_cast<float4*>(&sW[wrow][wcol + 4]) =
                *reinterpret_cast<const float4*>(wp + 4);
        }
        // build 16 k-values of this thread's edge column
        {
            float ew = s_ew[le];
            int kb = h16 * 16;   // local k base within the 32-k tile
            if (seg < 2) {
                int node = (seg == 0) ? s_dst[le] : s_src[le];
                const float4* mp = reinterpret_cast<const float4*>(
                    &g_m[(size_t)node * 64 + half * 32 + kb]);
                #pragma unroll
                for (int f = 0; f < 4; f++) {
                    float4 v = mp[f];
                    sIn[kb + f * 4 + 0][le] = ew * v.x;
                    sIn[kb + f * 4 + 1][le] = ew * v.y;
                    sIn[kb + f * 4 + 2][le] = ew * v.z;
                    sIn[kb + f * 4 + 3][le] = ew * v.w;
                }
            } else {
                float a0 = s_attr[le][0], a1 = s_attr[le][1], a2 = s_attr[le][2];
                #pragma unroll
                for (int f = 0; f < 4; f++) {
                    int k = half * 32 + kb + f * 4;   // channel index of ea
                    float4 w0 = *reinterpret_cast<const float4*>(&sWe[0][k]);
                    float4 w1 = *reinterpret_cast<const float4*>(&sWe[1][k]);
                    float4 w2 = *reinterpret_cast<const float4*>(&sWe[2][k]);
                    float4 bb = *reinterpret_cast<const float4*>(&sbe[k]);
                    sIn[kb + f * 4 + 0][le] = ew * (a0 * w0.x + a1 * w1.x + a2 * w2.x + bb.x);
                    sIn[kb + f * 4 + 1][le] = ew * (a0 * w0.y + a1 * w1.y + a2 * w2.y + bb.y);
                    sIn[kb + f * 4 + 2][le] = ew * (a0 * w0.z + a1 * w1.z + a2 * w2.z + bb.z);
                    sIn[kb + f * 4 + 3][le] = ew * (a0 * w0.w + a1 * w1.w + a2 * w2.w + bb.w);
                }
            }
        }
        __syncthreads();
        #pragma unroll
        for (int k = 0; k < 32; k++) micro8x4(acc, &sIn[k][0], &sW[k][0], tr, tc);
        __syncthreads();
    }

    // epilogue: atomic segment reductions keyed by dst
    float bpv[4];
    {
        float4 t = *reinterpret_cast<const float4*>(&sbpre[tc * 4]);
        bpv[0] = t.x; bpv[1] = t.y; bpv[2] = t.z; bpv[3] = t.w;
    }
    #pragma unroll
    for (int p = 0; p < 4; p++) {
        float v0[4], v1[4];
        #pragma unroll
        for (int j = 0; j < 4; j++) unpack2(acc[p][j], v0[j], v1[j]);
        int e0 = tr * 8 + 2 * p;
        #pragma unroll
        for (int pe = 0; pe < 2; pe++) {
            int e = e0 + pe;
            if (e < ne) {
                int d = s_dst[e];
                size_t base = (size_t)d * 64 + tc * 4;
                const float* vv = pe ? v1 : v0;
                #pragma unroll
                for (int j = 0; j < 4; j++) {
                    float h = vv[j] + bpv[j];
                    atomicAdd(&g_s1[base + j], h);
                    atomicAdd(&g_s2[base + j], h * h);
                    unsigned o = f2o(h);
                    atomicMin(&g_mn[base + j], o);
                    atomicMax(&g_mx[base + j], o);
                }
            }
        }
    }
}

// ---------------- per-node aggregate finalize ----------------
__global__ void node_kernel(int N) {
    int idx = blockIdx.x * 256 + threadIdx.x;
    if (idx >= N * CC) return;
    int n = idx >> 6, c = idx & 63;
    float cnt = g_cnt[n];
    float safe = fmaxf(cnt, 1.f);
    float inv = 1.f / safe;
    float mean = g_s1[idx] * inv;
    float msq  = g_s2[idx] * inv;
    float var  = msq - mean * mean;
    float stdv = sqrtf(fmaxf(var, 0.f) + 1e-5f);
    float mnf = 0.f, mxf = 0.f;
    if (cnt > 0.f) { mnf = o2f(g_mn[idx]); mxf = o2f(g_mx[idx]); }
    size_t b = (size_t)n * 256;
    g_agg[b + c]       = mean;
    g_agg[b + 64 + c]  = mnf;
    g_agg[b + 128 + c] = mxf;
    g_agg[b + 192 + c] = stdv;
    if (c == 0) {
        float avg = g_avgsum[0] / (float)N;
        float logd = logf(safe + 1.f);
        float a = logd / avg;
        g_a[n]  = a;
        g_ia[n] = a * (avg / logd);
    }
}

// ---------------- Wpost GEMM (K=832), on-the-fly z, 256 threads ----------------
__global__ void __launch_bounds__(256) gemm_post(const float* __restrict__ Wpost,
                                                 const float* __restrict__ bpost, int M) {
    __shared__ float As[16][128];
    __shared__ float Bs[16][64];
    int tid = threadIdx.x;
    int tr = tid / 16, tc = tid % 16;
    int mBase = blockIdx.x * 128;
    ull acc[4][4];
    #pragma unroll
    for (int p = 0; p < 4; p++)
        #pragma unroll
        for (int j = 0; j < 4; j++) acc[p][j] = 0ull;

    int ar = tid & 127;
    int ak = (tid >> 7) * 8;
    int brow = tid / 16;
    int bcol = (tid % 16) * 4;
    int m = mBase + ar;
    float sa = 0.f, sia = 0.f;
    if (m < M) { sa = g_a[m]; sia = g_ia[m]; }

    for (int k0 = 0; k0 < 832; k0 += 16) {
        #pragma unroll
        for (int q = 0; q < 2; q++) {
            float4 av = make_float4(0.f, 0.f, 0.f, 0.f);
            int k = k0 + ak + q * 4;
            if (m < M) {
                float sc = 1.f;
                const float* src;
                if (k < 64)       src = &g_m[(size_t)m * 64 + k];
                else if (k < 320) src = &g_agg[(size_t)m * 256 + (k - 64)];
                else if (k < 576) { src = &g_agg[(size_t)m * 256 + (k - 320)]; sc = sa; }
                else              { src = &g_agg[(size_t)m * 256 + (k - 576)]; sc = sia; }
                av = *reinterpret_cast<const float4*>(src);
                av.x *= sc; av.y *= sc; av.z *= sc; av.w *= sc;
            }
            int kl = ak + q * 4;
            As[kl + 0][ar] = av.x; As[kl + 1][ar] = av.y;
            As[kl + 2][ar] = av.z; As[kl + 3][ar] = av.w;
        }
        *reinterpret_cast<float4*>(&Bs[brow][bcol]) =
            *reinterpret_cast<const float4*>(&Wpost[(size_t)(k0 + brow) * 64 + bcol]);
        __syncthreads();
        #pragma unroll
        for (int k = 0; k < 16; k++) micro8x4(acc, &As[k][0], &Bs[k][0], tr, tc);
        __syncthreads();
    }

    float4 t = *reinterpret_cast<const float4*>(&bpost[tc * 4]);
    float bs[4] = {t.x, t.y, t.z, t.w};
    #pragma unroll
    for (int p = 0; p < 4; p++) {
        float v0[4], v1[4];
        #pragma unroll
        for (int j = 0; j < 4; j++) unpack2(acc[p][j], v0[j], v1[j]);
        int m0 = mBase + tr * 8 + 2 * p;
        if (m0 < M) {
            float4 o = make_float4(v0[0] + bs[0], v0[1] + bs[1], v0[2] + bs[2], v0[3] + bs[3]);
            *reinterpret_cast<float4*>(&g_out_node[(size_t)m0 * 64 + tc * 4]) = o;
        }
        if (m0 + 1 < M) {
            float4 o = make_float4(v1[0] + bs[0], v1[1] + bs[1], v1[2] + bs[2], v1[3] + bs[3]);
            *reinterpret_cast<float4*>(&g_out_node[(size_t)(m0 + 1) * 64 + tc * 4]) = o;
        }
    }
}

// ---------------- GRU elementwise ----------------
__global__ void gru_kernel(const float* __restrict__ x, float* __restrict__ out, int N) {
    int idx = blockIdx.x * 256 + threadIdx.x;
    if (idx >= N * CC) return;
    int n = idx >> 6, c = idx & 63;
    size_t b = (size_t)n * 192;
    float ir = g_gi[b + c],        hr = g_gh[b + c];
    float iz = g_gi[b + 64 + c],   hz = g_gh[b + 64 + c];
    float in_ = g_gi[b + 128 + c], hn = g_gh[b + 128 + c];
    float r = 1.f / (1.f + expf(-(ir + hr)));
    float z = 1.f / (1.f + expf(-(iz + hz)));
    float nn = tanhf(in_ + r * hn);
    out[idx] = (1.f - z) * nn + z * x[idx];
}

// ---------------- launch ----------------
extern "C" void kernel_launch(void* const* d_in, const int* in_sizes, int n_in,
                              void* d_out, int out_size) {
    const float* x         = (const float*)d_in[0];
    const float* edge_attr = (const float*)d_in[1];
    const float* deg_hist  = (const float*)d_in[2];
    const float* W         = (const float*)d_in[3];
    const float* We        = (const float*)d_in[4];
    const float* be        = (const float*)d_in[5];
    const float* Wpre      = (const float*)d_in[6];
    const float* bpre      = (const float*)d_in[7];
    const float* Wpost     = (const float*)d_in[8];
    const float* bpost     = (const float*)d_in[9];
    const float* Wih       = (const float*)d_in[10];
    const float* bih       = (const float*)d_in[11];
    const float* Whh       = (const float*)d_in[12];
    const float* bhh       = (const float*)d_in[13];
    const int*   edge_index = (const int*)d_in[14];

    int N = in_sizes[0] / CC;
    int E = in_sizes[14] / 2;

    float *pm, *pon, *pgi, *pgh;
    cudaGetSymbolAddress((void**)&pm,  g_m);
    cudaGetSymbolAddress((void**)&pon, g_out_node);
    cudaGetSymbolAddress((void**)&pgi, g_gi);
    cudaGetSymbolAddress((void**)&pgh, g_gh);

    int nodeElems = N * CC;
    int mBlocks = (N + 127) / 128;
    init_kernel<<<(nodeElems + 255) / 256, 256>>>(N);
    avglog_kernel<<<(N + 255) / 256, 256>>>(deg_hist, N);
    gemm256<<<dim3(1, mBlocks), 256>>>(x, W, nullptr, pm, N, 64, 64);
    edge_kernel<<<(E + 127) / 128, 256>>>(edge_attr, edge_index, Wpre, We, be, bpre, E);
    node_kernel<<<(nodeElems + 255) / 256, 256>>>(N);
    gemm_post<<<mBlocks, 256>>>(Wpost, bpost, N);
    gemm256<<<dim3(3, mBlocks), 256>>>(pon, Wih, bih, pgi, N, 192, 64);
    gemm256<<<dim3(3, mBlocks), 256>>>(x, Whh, bhh, pgh, N, 192, 64);
    gru_kernel<<<(nodeElems + 255) / 256, 256>>>(x, (float*)d_out, N);
}

// round 5
// speedup vs baseline: 1.4863x; 1.1162x over previous
#include <cuda_runtime.h>
#include <math.h>
#include <stdint.h>

#define NN 50000
#define EE 800000
#define CC 64

typedef unsigned long long ull;

// ---------------- scratch ----------------
__device__ float g_m[NN * CC];
__device__ float g_h[EE * CC];          // per-edge MLP output (205 MB)
__device__ int   g_cnt_i[NN];
__device__ int   g_off[NN + 1];
__device__ int   g_cur[NN];
__device__ int   g_eid[EE];
__device__ float g_agg[NN * 4 * CC];
__device__ float g_a[NN];
__device__ float g_ia[NN];
__device__ float g_out_node[NN * CC];
__device__ float g_gi[NN * 3 * CC];
__device__ float g_gh[NN * 3 * CC];
__device__ float g_avgsum[1];

// ---------------- packed f32x2 helpers ----------------
__device__ __forceinline__ ull pack2(float lo, float hi) {
    ull r;
    asm("mov.b64 %0, {%1, %2};" : "=l"(r) : "f"(lo), "f"(hi));
    return r;
}
__device__ __forceinline__ void unpack2(ull v, float& lo, float& hi) {
    asm("mov.b64 {%0, %1}, %2;" : "=f"(lo), "=f"(hi) : "l"(v));
}
__device__ __forceinline__ void fma2(ull& d, ull a, ull b) {
    asm("fma.rn.f32x2 %0, %1, %2, %0;" : "+l"(d) : "l"(a), "l"(b));
}

// 4(rows)x8(ch) micro-step, FFMA2 packed along channels, B warp-uniform (broadcast).
// acc[e][j]: e = row (lane*4+e), j = channel pair (cg*8 + 2j, 2j+1).
__device__ __forceinline__ void micro4x8(ull acc[4][4],
                                         const float* __restrict__ As_k,  // 128 wide
                                         const float* __restrict__ Bs_k,  // 64 wide
                                         int lane, int cg) {
    float4 a = *reinterpret_cast<const float4*>(As_k + lane * 4);
    float4 b0 = *reinterpret_cast<const float4*>(Bs_k + cg * 8);
    float4 b1 = *reinterpret_cast<const float4*>(Bs_k + cg * 8 + 4);
    ull bp[4] = {pack2(b0.x, b0.y), pack2(b0.z, b0.w),
                 pack2(b1.x, b1.y), pack2(b1.z, b1.w)};
    ull ad[4] = {pack2(a.x, a.x), pack2(a.y, a.y), pack2(a.z, a.z), pack2(a.w, a.w)};
    #pragma unroll
    for (int e = 0; e < 4; e++)
        #pragma unroll
        for (int j = 0; j < 4; j++) fma2(acc[e][j], ad[e], bp[j]);
}

// ---------------- init ----------------
__global__ void init_kernel(int N) {
    int idx = blockIdx.x * 256 + threadIdx.x;
    if (idx < N) g_cnt_i[idx] = 0;
    if (idx == 0) g_avgsum[0] = 0.f;
}

// ---------------- avg_log ----------------
__global__ void avglog_kernel(const float* __restrict__ deg_hist, int N) {
    int idx = blockIdx.x * 256 + threadIdx.x;
    float v = (idx < N) ? logf(deg_hist[idx] + 1.f) : 0.f;
    #pragma unroll
    for (int o = 16; o; o >>= 1) v += __shfl_down_sync(0xFFFFFFFFu, v, o);
    __shared__ float sred[8];
    if ((threadIdx.x & 31) == 0) sred[threadIdx.x >> 5] = v;
    __syncthreads();
    if (threadIdx.x < 8) {
        v = sred[threadIdx.x];
        #pragma unroll
        for (int o = 4; o; o >>= 1) v += __shfl_down_sync(0xFFu, v, o);
        if (threadIdx.x == 0) atomicAdd(&g_avgsum[0], v);
    }
}

// ---------------- CSR build ----------------
__global__ void count_kernel(const int* __restrict__ edge_index, int E) {
    int idx = blockIdx.x * 256 + threadIdx.x;
    if (idx < E) atomicAdd(&g_cnt_i[edge_index[E + idx]], 1);
}

__global__ void __launch_bounds__(1024) scan_kernel(int N, int E) {
    __shared__ int sh[1024];
    int tid = threadIdx.x;
    int per = (N + 1023) / 1024;
    int start = tid * per;
    int end = start + per; if (end > N) end = N;
    int s = 0;
    for (int i = start; i < end; i++) s += g_cnt_i[i];
    sh[tid] = s;
    __syncthreads();
    // inclusive scan
    for (int d = 1; d < 1024; d <<= 1) {
        int v = (tid >= d) ? sh[tid - d] : 0;
        __syncthreads();
        sh[tid] += v;
        __syncthreads();
    }
    int running = sh[tid] - s;   // exclusive base
    for (int i = start; i < end; i++) {
        g_off[i] = running;
        g_cur[i] = running;
        running += g_cnt_i[i];
    }
    if (tid == 1023) g_off[N] = E;
}

__global__ void scatter_kernel(const int* __restrict__ edge_index, int E) {
    int idx = blockIdx.x * 256 + threadIdx.x;
    if (idx < E) {
        int d = edge_index[E + idx];
        int pos = atomicAdd(&g_cur[d], 1);
        g_eid[pos] = idx;
    }
}

// ---------------- SGEMM: BM=128, BN=64, BK=16, 256 threads, warp-uniform B ----------------
__global__ void __launch_bounds__(256) gemm256(const float* __restrict__ A,
                                               const float* __restrict__ B,
                                               const float* __restrict__ bias,
                                               float* __restrict__ Cout,
                                               int M, int Ncol, int K) {
    __shared__ float As[16][128];
    __shared__ float Bs[16][64];
    int tid = threadIdx.x;
    int lane = tid & 31;
    int cg = tid >> 5;           // warp id = channel group (8 ch)
    int mBase = blockIdx.y * 128;
    int nBase = blockIdx.x * 64;
    ull acc[4][4];
    #pragma unroll
    for (int e = 0; e < 4; e++)
        #pragma unroll
        for (int j = 0; j < 4; j++) acc[e][j] = 0ull;

    int ar = tid & 127;
    int ak = (tid >> 7) * 8;
    int brow = tid / 16;
    int bcol = (tid % 16) * 4;

    for (int k0 = 0; k0 < K; k0 += 16) {
        int m = mBase + ar;
        float4 a0 = make_float4(0.f, 0.f, 0.f, 0.f), a1 = a0;
        if (m < M) {
            const float* ap = &A[(size_t)m * K + k0 + ak];
            a0 = *reinterpret_cast<const float4*>(ap);
            a1 = *reinterpret_cast<const float4*>(ap + 4);
        }
        As[ak + 0][ar] = a0.x; As[ak + 1][ar] = a0.y;
        As[ak + 2][ar] = a0.z; As[ak + 3][ar] = a0.w;
        As[ak + 4][ar] = a1.x; As[ak + 5][ar] = a1.y;
        As[ak + 6][ar] = a1.z; As[ak + 7][ar] = a1.w;
        *reinterpret_cast<float4*>(&Bs[brow][bcol]) =
            *reinterpret_cast<const float4*>(&B[(size_t)(k0 + brow) * Ncol + nBase + bcol]);
        __syncthreads();
        #pragma unroll
        for (int k = 0; k < 16; k++) micro4x8(acc, &As[k][0], &Bs[k][0], lane, cg);
        __syncthreads();
    }

    float bs[8] = {0, 0, 0, 0, 0, 0, 0, 0};
    if (bias) {
        float4 t0 = *reinterpret_cast<const float4*>(&bias[nBase + cg * 8]);
        float4 t1 = *reinterpret_cast<const float4*>(&bias[nBase + cg * 8 + 4]);
        bs[0] = t0.x; bs[1] = t0.y; bs[2] = t0.z; bs[3] = t0.w;
        bs[4] = t1.x; bs[5] = t1.y; bs[6] = t1.z; bs[7] = t1.w;
    }
    #pragma unroll
    for (int e = 0; e < 4; e++) {
        int m = mBase + lane * 4 + e;
        if (m < M) {
            float v[8];
            #pragma unroll
            for (int j = 0; j < 4; j++) unpack2(acc[e][j], v[2 * j], v[2 * j + 1]);
            float* cp = &Cout[(size_t)m * Ncol + nBase + cg * 8];
            *reinterpret_cast<float4*>(cp) =
                make_float4(v[0] + bs[0], v[1] + bs[1], v[2] + bs[2], v[3] + bs[3]);
            *reinterpret_cast<float4*>(cp + 4) =
                make_float4(v[4] + bs[4], v[5] + bs[5], v[6] + bs[6], v[7] + bs[7]);
        }
    }
}

// ---------------- edge kernel: MLP -> stream h to gmem (no atomics) ----------------
__global__ void __launch_bounds__(256) edge_kernel(const float* __restrict__ edge_attr,
                                                   const int* __restrict__ edge_index,
                                                   const float* __restrict__ Wpre,
                                                   const float* __restrict__ We,
                                                   const float* __restrict__ be,
                                                   const float* __restrict__ bpre,
                                                   int E) {
    __shared__ float sIn[32][128];
    __shared__ float sW[32][64];
    __shared__ int   s_src[128], s_dst[128];
    __shared__ float s_ew[128];
    __shared__ float s_attr[128][3];
    __shared__ float sWe[3][64];
    __shared__ float sbe[64];
    __shared__ float sbpre[64];

    int tid = threadIdx.x;
    int lane = tid & 31;
    int cg = tid >> 5;
    int eBase = blockIdx.x * 128;
    int ne = E - eBase; if (ne > 128) ne = 128;

    if (tid < 128) {
        bool v = tid < ne;
        int e = eBase + (v ? tid : 0);
        s_src[tid] = edge_index[e];
        s_dst[tid] = edge_index[E + e];
        float4 a4 = *reinterpret_cast<const float4*>(&edge_attr[(size_t)e * 4]);
        s_attr[tid][0] = a4.x; s_attr[tid][1] = a4.y; s_attr[tid][2] = a4.z;
        s_ew[tid] = v ? a4.w : 0.f;
    } else {
        int t = tid - 128;
        if (t < 64) {
            sbe[t] = be[t];
            sbpre[t] = bpre[t];
            sWe[0][t] = We[t];
            sWe[1][t] = We[64 + t];
            sWe[2][t] = We[128 + t];
        }
    }
    __syncthreads();

    ull acc[4][4];
    #pragma unroll
    for (int e = 0; e < 4; e++)
        #pragma unroll
        for (int j = 0; j < 4; j++) acc[e][j] = 0ull;

    int le  = tid & 127;
    int h16 = tid >> 7;
    int wrow = tid / 8;
    int wcol = (tid % 8) * 8;

    #pragma unroll 1
    for (int sp = 0; sp < 6; sp++) {
        int seg = sp >> 1;
        int half = sp & 1;
        {
            const float* wp = &Wpre[(size_t)(seg * 64 + half * 32 + wrow) * 64 + wcol];
            *reinterpret_cast<float4*>(&sW[wrow][wcol]) = *reinterpret_cast<const float4*>(wp);
            *reinterpret_cast<float4*>(&sW[wrow][wcol + 4]) =
                *reinterpret_cast<const float4*>(wp + 4);
        }
        {
            float ew = s_ew[le];
            int kb = h16 * 16;
            if (seg < 2) {
                int node = (seg == 0) ? s_dst[le] : s_src[le];
                const float4* mp = reinterpret_cast<const float4*>(
                    &g_m[(size_t)node * 64 + half * 32 + kb]);
                #pragma unroll
                for (int f = 0; f < 4; f++) {
                    float4 v = mp[f];
                    sIn[kb + f * 4 + 0][le] = ew * v.x;
                    sIn[kb + f * 4 + 1][le] = ew * v.y;
                    sIn[kb + f * 4 + 2][le] = ew * v.z;
                    sIn[kb + f * 4 + 3][le] = ew * v.w;
                }
            } else {
                float a0 = s_attr[le][0], a1 = s_attr[le][1], a2 = s_attr[le][2];
                #pragma unroll
                for (int f = 0; f < 4; f++) {
                    int k = half * 32 + kb + f * 4;
                    float4 w0 = *reinterpret_cast<const float4*>(&sWe[0][k]);
                    float4 w1 = *reinterpret_cast<const float4*>(&sWe[1][k]);
                    float4 w2 = *reinterpret_cast<const float4*>(&sWe[2][k]);
                    float4 bb = *reinterpret_cast<const float4*>(&sbe[k]);
                    sIn[kb + f * 4 + 0][le] = ew * (a0 * w0.x + a1 * w1.x + a2 * w2.x + bb.x);
                    sIn[kb + f * 4 + 1][le] = ew * (a0 * w0.y + a1 * w1.y + a2 * w2.y + bb.y);
                    sIn[kb + f * 4 + 2][le] = ew * (a0 * w0.z + a1 * w1.z + a2 * w2.z + bb.z);
                    sIn[kb + f * 4 + 3][le] = ew * (a0 * w0.w + a1 * w1.w + a2 * w2.w + bb.w);
                }
            }
        }
        __syncthreads();
        #pragma unroll
        for (int k = 0; k < 32; k++) micro4x8(acc, &sIn[k][0], &sW[k][0], lane, cg);
        __syncthreads();
    }

    // epilogue: h = acc + bpre, streamed to g_h (coalesced within warp rows)
    float bp0[4], bp1[4];
    {
        float4 t0 = *reinterpret_cast<const float4*>(&sbpre[cg * 8]);
        float4 t1 = *reinterpret_cast<const float4*>(&sbpre[cg * 8 + 4]);
        bp0[0] = t0.x; bp0[1] = t0.y; bp0[2] = t0.z; bp0[3] = t0.w;
        bp1[0] = t1.x; bp1[1] = t1.y; bp1[2] = t1.z; bp1[3] = t1.w;
    }
    #pragma unroll
    for (int e = 0; e < 4; e++) {
        int el = lane * 4 + e;
        if (el < ne) {
            float v[8];
            #pragma unroll
            for (int j = 0; j < 4; j++) unpack2(acc[e][j], v[2 * j], v[2 * j + 1]);
            float* hp = &g_h[(size_t)(eBase + el) * 64 + cg * 8];
            *reinterpret_cast<float4*>(hp) =
                make_float4(v[0] + bp0[0], v[1] + bp0[1], v[2] + bp0[2], v[3] + bp0[3]);
            *reinterpret_cast<float4*>(hp + 4) =
                make_float4(v[4] + bp1[0], v[5] + bp1[1], v[6] + bp1[2], v[7] + bp1[3]);
        }
    }
}

// ---------------- node reduce: warp per node, CSR gather over h ----------------
__global__ void __launch_bounds__(256) node_reduce(int N) {
    int lane = threadIdx.x & 31;
    int n = blockIdx.x * 8 + (threadIdx.x >> 5);
    if (n >= N) return;
    int off0 = g_off[n], off1 = g_off[n + 1];
    int deg = off1 - off0;
    float s1a = 0.f, s2a = 0.f, s1b = 0.f, s2b = 0.f;
    float mna = 3.4e38f, mxa = -3.4e38f, mnb = 3.4e38f, mxb = -3.4e38f;
    for (int i = off0; i < off1; i++) {
        int eid = g_eid[i];
        const float* hp = &g_h[(size_t)eid * 64];
        float va = hp[lane];
        float vb = hp[lane + 32];
        s1a += va; s2a += va * va; mna = fminf(mna, va); mxa = fmaxf(mxa, va);
        s1b += vb; s2b += vb * vb; mnb = fminf(mnb, vb); mxb = fmaxf(mxb, vb);
    }
    float cnt = (float)deg;
    float safe = fmaxf(cnt, 1.f);
    float inv = 1.f / safe;
    float meana = s1a * inv, meanb = s1b * inv;
    float stda = sqrtf(fmaxf(s2a * inv - meana * meana, 0.f) + 1e-5f);
    float stdb = sqrtf(fmaxf(s2b * inv - meanb * meanb, 0.f) + 1e-5f);
    if (deg == 0) { mna = 0.f; mxa = 0.f; mnb = 0.f; mxb = 0.f; }
    size_t b = (size_t)n * 256;
    g_agg[b + lane]            = meana;
    g_agg[b + lane + 32]       = meanb;
    g_agg[b + 64 + lane]       = mna;
    g_agg[b + 64 + lane + 32]  = mnb;
    g_agg[b + 128 + lane]      = mxa;
    g_agg[b + 128 + lane + 32] = mxb;
    g_agg[b + 192 + lane]      = stda;
    g_agg[b + 192 + lane + 32] = stdb;
    if (lane == 0) {
        float avg = g_avgsum[0] / (float)N;
        float logd = logf(safe + 1.f);
        float a = logd / avg;
        g_a[n]  = a;
        g_ia[n] = a * (avg / logd);   // fp-composed o3 scale
    }
}

// ---------------- Wpost GEMM (K=832), on-the-fly z ----------------
__global__ void __launch_bounds__(256) gemm_post(const float* __restrict__ Wpost,
                                                 const float* __restrict__ bpost, int M) {
    __shared__ float As[16][128];
    __shared__ float Bs[16][64];
    int tid = threadIdx.x;
    int lane = tid & 31;
    int cg = tid >> 5;
    int mBase = blockIdx.x * 128;
    ull acc[4][4];
    #pragma unroll
    for (int e = 0; e < 4; e++)
        #pragma unroll
        for (int j = 0; j < 4; j++) acc[e][j] = 0ull;

    int ar = tid & 127;
    int ak = (tid >> 7) * 8;
    int brow = tid / 16;
    int bcol = (tid % 16) * 4;
    int m = mBase + ar;
    float sa = 0.f, sia = 0.f;
    if (m < M) { sa = g_a[m]; sia = g_ia[m]; }

    for (int k0 = 0; k0 < 832; k0 += 16) {
        #pragma unroll
        for (int q = 0; q < 2; q++) {
            float4 av = make_float4(0.f, 0.f, 0.f, 0.f);
            int k = k0 + ak + q * 4;
            if (m < M) {
                float sc = 1.f;
                const float* src;
                if (k < 64)       src = &g_m[(size_t)m * 64 + k];
                else if (k < 320) src = &g_agg[(size_t)m * 256 + (k - 64)];
                else if (k < 576) { src = &g_agg[(size_t)m * 256 + (k - 320)]; sc = sa; }
                else              { src = &g_agg[(size_t)m * 256 + (k - 576)]; sc = sia; }
                av = *reinterpret_cast<const float4*>(src);
                av.x *= sc; av.y *= sc; av.z *= sc; av.w *= sc;
            }
            int kl = ak + q * 4;
            As[kl + 0][ar] = av.x; As[kl + 1][ar] = av.y;
            As[kl + 2][ar] = av.z; As[kl + 3][ar] = av.w;
        }
        *reinterpret_cast<float4*>(&Bs[brow][bcol]) =
            *reinterpret_cast<const float4*>(&Wpost[(size_t)(k0 + brow) * 64 + bcol]);
        __syncthreads();
        #pragma unroll
        for (int k = 0; k < 16; k++) micro4x8(acc, &As[k][0], &Bs[k][0], lane, cg);
        __syncthreads();
    }

    float4 t0 = *reinterpret_cast<const float4*>(&bpost[cg * 8]);
    float4 t1 = *reinterpret_cast<const float4*>(&bpost[cg * 8 + 4]);
    float bs[8] = {t0.x, t0.y, t0.z, t0.w, t1.x, t1.y, t1.z, t1.w};
    #pragma unroll
    for (int e = 0; e < 4; e++) {
        int mm = mBase + lane * 4 + e;
        if (mm < M) {
            float v[8];
            #pragma unroll
            for (int j = 0; j < 4; j++) unpack2(acc[e][j], v[2 * j], v[2 * j + 1]);
            float* cp = &g_out_node[(size_t)mm * 64 + cg * 8];
            *reinterpret_cast<float4*>(cp) =
                make_float4(v[0] + bs[0], v[1] + bs[1], v[2] + bs[2], v[3] + bs[3]);
            *reinterpret_cast<float4*>(cp + 4) =
                make_float4(v[4] + bs[4], v[5] + bs[5], v[6] + bs[6], v[7] + bs[7]);
        }
    }
}

// ---------------- GRU elementwise ----------------
__global__ void gru_kernel(const float* __restrict__ x, float* __restrict__ out, int N) {
    int idx = blockIdx.x * 256 + threadIdx.x;
    if (idx >= N * CC) return;
    int n = idx >> 6, c = idx & 63;
    size_t b = (size_t)n * 192;
    float ir = g_gi[b + c],        hr = g_gh[b + c];
    float iz = g_gi[b + 64 + c],   hz = g_gh[b + 64 + c];
    float in_ = g_gi[b + 128 + c], hn = g_gh[b + 128 + c];
    float r = 1.f / (1.f + expf(-(ir + hr)));
    float z = 1.f / (1.f + expf(-(iz + hz)));
    float nn = tanhf(in_ + r * hn);
    out[idx] = (1.f - z) * nn + z * x[idx];
}

// ---------------- launch ----------------
extern "C" void kernel_launch(void* const* d_in, const int* in_sizes, int n_in,
                              void* d_out, int out_size) {
    const float* x         = (const float*)d_in[0];
    const float* edge_attr = (const float*)d_in[1];
    const float* deg_hist  = (const float*)d_in[2];
    const float* W         = (const float*)d_in[3];
    const float* We        = (const float*)d_in[4];
    const float* be        = (const float*)d_in[5];
    const float* Wpre      = (const float*)d_in[6];
    const float* bpre      = (const float*)d_in[7];
    const float* Wpost     = (const float*)d_in[8];
    const float* bpost     = (const float*)d_in[9];
    const float* Wih       = (const float*)d_in[10];
    const float* bih       = (const float*)d_in[11];
    const float* Whh       = (const float*)d_in[12];
    const float* bhh       = (const float*)d_in[13];
    const int*   edge_index = (const int*)d_in[14];

    int N = in_sizes[0] / CC;
    int E = in_sizes[14] / 2;

    float *pm, *pon, *pgi, *pgh;
    cudaGetSymbolAddress((void**)&pm,  g_m);
    cudaGetSymbolAddress((void**)&pon, g_out_node);
    cudaGetSymbolAddress((void**)&pgi, g_gi);
    cudaGetSymbolAddress((void**)&pgh, g_gh);

    int nodeElems = N * CC;
    int mBlocks = (N + 127) / 128;
    int eBlocks256 = (E + 255) / 256;

    init_kernel<<<(N + 255) / 256, 256>>>(N);
    avglog_kernel<<<(N + 255) / 256, 256>>>(deg_hist, N);
    count_kernel<<<eBlocks256, 256>>>(edge_index, E);
    gemm256<<<dim3(1, mBlocks), 256>>>(x, W, nullptr, pm, N, 64, 64);
    scan_kernel<<<1, 1024>>>(N, E);
    scatter_kernel<<<eBlocks256, 256>>>(edge_index, E);
    edge_kernel<<<(E + 127) / 128, 256>>>(edge_attr, edge_index, Wpre, We, be, bpre, E);
    node_reduce<<<(N + 7) / 8, 256>>>(N);
    gemm_post<<<mBlocks, 256>>>(Wpost, bpost, N);
    gemm256<<<dim3(3, mBlocks), 256>>>(pon, Wih, bih, pgi, N, 192, 64);
    gemm256<<<dim3(3, mBlocks), 256>>>(x, Whh, bhh, pgh, N, 192, 64);
    gru_kernel<<<(nodeElems + 255) / 256, 256>>>(x, (float*)d_out, N);
}

// round 6
// speedup vs baseline: 2.7212x; 1.8309x over previous
#include <cuda_runtime.h>
#include <math.h>
#include <stdint.h>

#define NN 50000
#define EE 800000
#define CC 64

typedef unsigned long long ull;

// ---------------- scratch ----------------
__device__ float g_m[NN * CC];          // x @ W
__device__ float g_p1[NN * CC];         // m @ Wpre[0:64]   (dst term)
__device__ float g_p2[NN * CC];         // m @ Wpre[64:128] (src term)
__device__ float g_C3[3 * CC];          // We @ Wpre[128:192]
__device__ float g_c3[CC];              // be @ Wpre[128:192]
__device__ int   g_cnt_i[NN];
__device__ int   g_off[NN + 1];
__device__ int   g_cur[NN];
__device__ int   g_eid[EE];
__device__ float g_agg[NN * 4 * CC];    // [mean | min | max | std]
__device__ float g_a[NN];
__device__ float g_ia[NN];
__device__ float g_out_node[NN * CC];
__device__ float g_gi[NN * 3 * CC];
__device__ float g_gh[NN * 3 * CC];
__device__ float g_avgsum[1];

// ---------------- packed f32x2 helpers ----------------
__device__ __forceinline__ ull pack2(float lo, float hi) {
    ull r;
    asm("mov.b64 %0, {%1, %2};" : "=l"(r) : "f"(lo), "f"(hi));
    return r;
}
__device__ __forceinline__ void unpack2(ull v, float& lo, float& hi) {
    asm("mov.b64 {%0, %1}, %2;" : "=f"(lo), "=f"(hi) : "l"(v));
}
__device__ __forceinline__ void fma2(ull& d, ull a, ull b) {
    asm("fma.rn.f32x2 %0, %1, %2, %0;" : "+l"(d) : "l"(a), "l"(b));
}

// 4(rows)x8(ch) micro-step, FFMA2 packed along channels, B warp-uniform (broadcast).
__device__ __forceinline__ void micro4x8(ull acc[4][4],
                                         const float* __restrict__ As_k,
                                         const float* __restrict__ Bs_k,
                                         int lane, int cg) {
    float4 a = *reinterpret_cast<const float4*>(As_k + lane * 4);
    float4 b0 = *reinterpret_cast<const float4*>(Bs_k + cg * 8);
    float4 b1 = *reinterpret_cast<const float4*>(Bs_k + cg * 8 + 4);
    ull bp[4] = {pack2(b0.x, b0.y), pack2(b0.z, b0.w),
                 pack2(b1.x, b1.y), pack2(b1.z, b1.w)};
    ull ad[4] = {pack2(a.x, a.x), pack2(a.y, a.y), pack2(a.z, a.z), pack2(a.w, a.w)};
    #pragma unroll
    for (int e = 0; e < 4; e++)
        #pragma unroll
        for (int j = 0; j < 4; j++) fma2(acc[e][j], ad[e], bp[j]);
}

// ---------------- init ----------------
__global__ void init_kernel(int N) {
    int idx = blockIdx.x * 256 + threadIdx.x;
    if (idx < N) g_cnt_i[idx] = 0;
    if (idx == 0) g_avgsum[0] = 0.f;
}

// ---------------- avg_log ----------------
__global__ void avglog_kernel(const float* __restrict__ deg_hist, int N) {
    int idx = blockIdx.x * 256 + threadIdx.x;
    float v = (idx < N) ? logf(deg_hist[idx] + 1.f) : 0.f;
    #pragma unroll
    for (int o = 16; o; o >>= 1) v += __shfl_down_sync(0xFFFFFFFFu, v, o);
    __shared__ float sred[8];
    if ((threadIdx.x & 31) == 0) sred[threadIdx.x >> 5] = v;
    __syncthreads();
    if (threadIdx.x < 8) {
        v = sred[threadIdx.x];
        #pragma unroll
        for (int o = 4; o; o >>= 1) v += __shfl_down_sync(0xFFu, v, o);
        if (threadIdx.x == 0) atomicAdd(&g_avgsum[0], v);
    }
}

// ---------------- CSR build ----------------
__global__ void count_kernel(const int* __restrict__ edge_index, int E) {
    int idx = blockIdx.x * 256 + threadIdx.x;
    if (idx < E) atomicAdd(&g_cnt_i[edge_index[E + idx]], 1);
}

__global__ void __launch_bounds__(1024) scan_kernel(int N, int E) {
    __shared__ int sh[1024];
    int tid = threadIdx.x;
    int per = (N + 1023) / 1024;
    int start = tid * per;
    int end = start + per; if (end > N) end = N;
    int s = 0;
    for (int i = start; i < end; i++) s += g_cnt_i[i];
    sh[tid] = s;
    __syncthreads();
    for (int d = 1; d < 1024; d <<= 1) {
        int v = (tid >= d) ? sh[tid - d] : 0;
        __syncthreads();
        sh[tid] += v;
        __syncthreads();
    }
    int running = sh[tid] - s;
    for (int i = start; i < end; i++) {
        g_off[i] = running;
        g_cur[i] = running;
        running += g_cnt_i[i];
    }
    if (tid == 1023) g_off[N] = E;
}

__global__ void scatter_kernel(const int* __restrict__ edge_index, int E) {
    int idx = blockIdx.x * 256 + threadIdx.x;
    if (idx < E) {
        int d = edge_index[E + idx];
        int pos = atomicAdd(&g_cur[d], 1);
        g_eid[pos] = idx;
    }
}

// ---------------- prep: C3 = We @ Wpre3, c3 = be @ Wpre3 ----------------
__global__ void prep_kernel(const float* __restrict__ We, const float* __restrict__ be,
                            const float* __restrict__ Wpre) {
    int c = threadIdx.x;   // 0..63
    const float* W3 = Wpre + 128 * 64;
    float a0 = 0.f, a1 = 0.f, a2 = 0.f, ab = 0.f;
    for (int j = 0; j < 64; j++) {
        float w = W3[j * 64 + c];
        a0 += We[j] * w;
        a1 += We[64 + j] * w;
        a2 += We[128 + j] * w;
        ab += be[j] * w;
    }
    g_C3[c] = a0;
    g_C3[64 + c] = a1;
    g_C3[128 + c] = a2;
    g_c3[c] = ab;
}

// ---------------- SGEMM: BM=128, BN=64, BK=16, 256 threads, warp-uniform B ----------------
__global__ void __launch_bounds__(256) gemm256(const float* __restrict__ A,
                                               const float* __restrict__ B,
                                               const float* __restrict__ bias,
                                               float* __restrict__ Cout,
                                               int M, int Ncol, int K) {
    __shared__ float As[16][128];
    __shared__ float Bs[16][64];
    int tid = threadIdx.x;
    int lane = tid & 31;
    int cg = tid >> 5;
    int mBase = blockIdx.y * 128;
    int nBase = blockIdx.x * 64;
    ull acc[4][4];
    #pragma unroll
    for (int e = 0; e < 4; e++)
        #pragma unroll
        for (int j = 0; j < 4; j++) acc[e][j] = 0ull;

    int ar = tid & 127;
    int ak = (tid >> 7) * 8;
    int brow = tid / 16;
    int bcol = (tid % 16) * 4;

    for (int k0 = 0; k0 < K; k0 += 16) {
        int m = mBase + ar;
        float4 a0 = make_float4(0.f, 0.f, 0.f, 0.f), a1 = a0;
        if (m < M) {
            const float* ap = &A[(size_t)m * K + k0 + ak];
            a0 = *reinterpret_cast<const float4*>(ap);
            a1 = *reinterpret_cast<const float4*>(ap + 4);
        }
        As[ak + 0][ar] = a0.x; As[ak + 1][ar] = a0.y;
        As[ak + 2][ar] = a0.z; As[ak + 3][ar] = a0.w;
        As[ak + 4][ar] = a1.x; As[ak + 5][ar] = a1.y;
        As[ak + 6][ar] = a1.z; As[ak + 7][ar] = a1.w;
        *reinterpret_cast<float4*>(&Bs[brow][bcol]) =
            *reinterpret_cast<const float4*>(&B[(size_t)(k0 + brow) * Ncol + nBase + bcol]);
        __syncthreads();
        #pragma unroll
        for (int k = 0; k < 16; k++) micro4x8(acc, &As[k][0], &Bs[k][0], lane, cg);
        __syncthreads();
    }

    float bs[8] = {0, 0, 0, 0, 0, 0, 0, 0};
    if (bias) {
        float4 t0 = *reinterpret_cast<const float4*>(&bias[nBase + cg * 8]);
        float4 t1 = *reinterpret_cast<const float4*>(&bias[nBase + cg * 8 + 4]);
        bs[0] = t0.x; bs[1] = t0.y; bs[2] = t0.z; bs[3] = t0.w;
        bs[4] = t1.x; bs[5] = t1.y; bs[6] = t1.z; bs[7] = t1.w;
    }
    #pragma unroll
    for (int e = 0; e < 4; e++) {
        int m = mBase + lane * 4 + e;
        if (m < M) {
            float v[8];
            #pragma unroll
            for (int j = 0; j < 4; j++) unpack2(acc[e][j], v[2 * j], v[2 * j + 1]);
            float* cp = &Cout[(size_t)m * Ncol + nBase + cg * 8];
            *reinterpret_cast<float4*>(cp) =
                make_float4(v[0] + bs[0], v[1] + bs[1], v[2] + bs[2], v[3] + bs[3]);
            *reinterpret_cast<float4*>(cp + 4) =
                make_float4(v[4] + bs[4], v[5] + bs[5], v[6] + bs[6], v[7] + bs[7]);
        }
    }
}

// ---------------- fused edge compute + node reduce (warp per node) ----------------
// h[e] = ew*(P1[dst] + P2[src] + attr@C3 + c3) + bpre ; stats over dst segments.
__global__ void __launch_bounds__(256) node_edge_reduce(const int* __restrict__ edge_index,
                                                        const float* __restrict__ edge_attr,
                                                        const float* __restrict__ bpre,
                                                        int N, int E) {
    int lane = threadIdx.x & 31;
    int n = blockIdx.x * 8 + (threadIdx.x >> 5);
    if (n >= N) return;
    int off0 = g_off[n], off1 = g_off[n + 1];
    int deg = off1 - off0;

    // loop-invariant per-channel terms (lane -> channels lane, lane+32)
    float basea = g_p1[(size_t)n * 64 + lane] + g_c3[lane];
    float baseb = g_p1[(size_t)n * 64 + lane + 32] + g_c3[lane + 32];
    float c30a = g_C3[lane],        c30b = g_C3[lane + 32];
    float c31a = g_C3[64 + lane],   c31b = g_C3[64 + lane + 32];
    float c32a = g_C3[128 + lane],  c32b = g_C3[128 + lane + 32];
    float bpa = bpre[lane], bpb = bpre[lane + 32];

    float s1a = 0.f, s2a = 0.f, s1b = 0.f, s2b = 0.f;
    float mna = 3.4e38f, mxa = -3.4e38f, mnb = 3.4e38f, mxb = -3.4e38f;

    // software-pipelined gather: prefetch next (eid -> src, attr)
    int src_n = 0;
    float4 at_n = make_float4(0.f, 0.f, 0.f, 0.f);
    if (deg > 0) {
        int eid = g_eid[off0];
        src_n = edge_index[eid];
        at_n = *reinterpret_cast<const float4*>(&edge_attr[(size_t)eid * 4]);
    }
    for (int i = off0; i < off1; i++) {
        int src = src_n;
        float4 at = at_n;
        const float* p2 = &g_p2[(size_t)src * 64];
        float va = p2[lane];
        float vb = p2[lane + 32];
        if (i + 1 < off1) {
            int eid = g_eid[i + 1];
            src_n = edge_index[eid];
            at_n = *reinterpret_cast<const float4*>(&edge_attr[(size_t)eid * 4]);
        }
        float ew = at.w;
        float ha = ew * (basea + va + at.x * c30a + at.y * c31a + at.z * c32a) + bpa;
        float hb = ew * (baseb + vb + at.x * c30b + at.y * c31b + at.z * c32b) + bpb;
        s1a += ha; s2a += ha * ha;
        mna = fminf(mna, ha); mxa = fmaxf(mxa, ha);
        s1b += hb; s2b += hb * hb;
        mnb = fminf(mnb, hb); mxb = fmaxf(mxb, hb);
    }

    float cnt = (float)deg;
    float safe = fmaxf(cnt, 1.f);
    float inv = 1.f / safe;
    float meana = s1a * inv, meanb = s1b * inv;
    float stda = sqrtf(fmaxf(s2a * inv - meana * meana, 0.f) + 1e-5f);
    float stdb = sqrtf(fmaxf(s2b * inv - meanb * meanb, 0.f) + 1e-5f);
    if (deg == 0) { mna = 0.f; mxa = 0.f; mnb = 0.f; mxb = 0.f; }
    size_t b = (size_t)n * 256;
    g_agg[b + lane]            = meana;
    g_agg[b + lane + 32]       = meanb;
    g_agg[b + 64 + lane]       = mna;
    g_agg[b + 64 + lane + 32]  = mnb;
    g_agg[b + 128 + lane]      = mxa;
    g_agg[b + 128 + lane + 32] = mxb;
    g_agg[b + 192 + lane]      = stda;
    g_agg[b + 192 + lane + 32] = stdb;
    if (lane == 0) {
        float avg = g_avgsum[0] / (float)N;
        float logd = logf(safe + 1.f);
        float a = logd / avg;
        g_a[n]  = a;
        g_ia[n] = a * (avg / logd);   // fp-composed o3 scale
    }
}

// ---------------- Wpost GEMM (K=832), on-the-fly z ----------------
__global__ void __launch_bounds__(256) gemm_post(const float* __restrict__ Wpost,
                                                 const float* __restrict__ bpost, int M) {
    __shared__ float As[16][128];
    __shared__ float Bs[16][64];
    int tid = threadIdx.x;
    int lane = tid & 31;
    int cg = tid >> 5;
    int mBase = blockIdx.x * 128;
    ull acc[4][4];
    #pragma unroll
    for (int e = 0; e < 4; e++)
        #pragma unroll
        for (int j = 0; j < 4; j++) acc[e][j] = 0ull;

    int ar = tid & 127;
    int ak = (tid >> 7) * 8;
    int brow = tid / 16;
    int bcol = (tid % 16) * 4;
    int m = mBase + ar;
    float sa = 0.f, sia = 0.f;
    if (m < M) { sa = g_a[m]; sia = g_ia[m]; }

    for (int k0 = 0; k0 < 832; k0 += 16) {
        #pragma unroll
        for (int q = 0; q < 2; q++) {
            float4 av = make_float4(0.f, 0.f, 0.f, 0.f);
            int k = k0 + ak + q * 4;
            if (m < M) {
                float sc = 1.f;
                const float* src;
                if (k < 64)       src = &g_m[(size_t)m * 64 + k];
                else if (k < 320) src = &g_agg[(size_t)m * 256 + (k - 64)];
                else if (k < 576) { src = &g_agg[(size_t)m * 256 + (k - 320)]; sc = sa; }
                else              { src = &g_agg[(size_t)m * 256 + (k - 576)]; sc = sia; }
                av = *reinterpret_cast<const float4*>(src);
                av.x *= sc; av.y *= sc; av.z *= sc; av.w *= sc;
            }
            int kl = ak + q * 4;
            As[kl + 0][ar] = av.x; As[kl + 1][ar] = av.y;
            As[kl + 2][ar] = av.z; As[kl + 3][ar] = av.w;
        }
        *reinterpret_cast<float4*>(&Bs[brow][bcol]) =
            *reinterpret_cast<const float4*>(&Wpost[(size_t)(k0 + brow) * 64 + bcol]);
        __syncthreads();
        #pragma unroll
        for (int k = 0; k < 16; k++) micro4x8(acc, &As[k][0], &Bs[k][0], lane, cg);
        __syncthreads();
    }

    float4 t0 = *reinterpret_cast<const float4*>(&bpost[cg * 8]);
    float4 t1 = *reinterpret_cast<const float4*>(&bpost[cg * 8 + 4]);
    float bs[8] = {t0.x, t0.y, t0.z, t0.w, t1.x, t1.y, t1.z, t1.w};
    #pragma unroll
    for (int e = 0; e < 4; e++) {
        int mm = mBase + lane * 4 + e;
        if (mm < M) {
            float v[8];
            #pragma unroll
            for (int j = 0; j < 4; j++) unpack2(acc[e][j], v[2 * j], v[2 * j + 1]);
            float* cp = &g_out_node[(size_t)mm * 64 + cg * 8];
            *reinterpret_cast<float4*>(cp) =
                make_float4(v[0] + bs[0], v[1] + bs[1], v[2] + bs[2], v[3] + bs[3]);
            *reinterpret_cast<float4*>(cp + 4) =
                make_float4(v[4] + bs[4], v[5] + bs[5], v[6] + bs[6], v[7] + bs[7]);
        }
    }
}

// ---------------- GRU elementwise ----------------
__global__ void gru_kernel(const float* __restrict__ x, float* __restrict__ out, int N) {
    int idx = blockIdx.x * 256 + threadIdx.x;
    if (idx >= N * CC) return;
    int n = idx >> 6, c = idx & 63;
    size_t b = (size_t)n * 192;
    float ir = g_gi[b + c],        hr = g_gh[b + c];
    float iz = g_gi[b + 64 + c],   hz = g_gh[b + 64 + c];
    float in_ = g_gi[b + 128 + c], hn = g_gh[b + 128 + c];
    float r = 1.f / (1.f + expf(-(ir + hr)));
    float z = 1.f / (1.f + expf(-(iz + hz)));
    float nn = tanhf(in_ + r * hn);
    out[idx] = (1.f - z) * nn + z * x[idx];
}

// ---------------- launch ----------------
extern "C" void kernel_launch(void* const* d_in, const int* in_sizes, int n_in,
                              void* d_out, int out_size) {
    const float* x         = (const float*)d_in[0];
    const float* edge_attr = (const float*)d_in[1];
    const float* deg_hist  = (const float*)d_in[2];
    const float* W         = (const float*)d_in[3];
    const float* We        = (const float*)d_in[4];
    const float* be        = (const float*)d_in[5];
    const float* Wpre      = (const float*)d_in[6];
    const float* bpre      = (const float*)d_in[7];
    const float* Wpost     = (const float*)d_in[8];
    const float* bpost     = (const float*)d_in[9];
    const float* Wih       = (const float*)d_in[10];
    const float* bih       = (const float*)d_in[11];
    const float* Whh       = (const float*)d_in[12];
    const float* bhh       = (const float*)d_in[13];
    const int*   edge_index = (const int*)d_in[14];

    int N = in_sizes[0] / CC;
    int E = in_sizes[14] / 2;

    float *pm, *pp1, *pp2, *pon, *pgi, *pgh;
    cudaGetSymbolAddress((void**)&pm,  g_m);
    cudaGetSymbolAddress((void**)&pp1, g_p1);
    cudaGetSymbolAddress((void**)&pp2, g_p2);
    cudaGetSymbolAddress((void**)&pon, g_out_node);
    cudaGetSymbolAddress((void**)&pgi, g_gi);
    cudaGetSymbolAddress((void**)&pgh, g_gh);

    int nodeElems = N * CC;
    int mBlocks = (N + 127) / 128;
    int eBlocks256 = (E + 255) / 256;

    init_kernel<<<(N + 255) / 256, 256>>>(N);
    avglog_kernel<<<(N + 255) / 256, 256>>>(deg_hist, N);
    count_kernel<<<eBlocks256, 256>>>(edge_index, E);
    prep_kernel<<<1, 64>>>(We, be, Wpre);
    gemm256<<<dim3(1, mBlocks), 256>>>(x, W, nullptr, pm, N, 64, 64);
    scan_kernel<<<1, 1024>>>(N, E);
    scatter_kernel<<<eBlocks256, 256>>>(edge_index, E);
    gemm256<<<dim3(1, mBlocks), 256>>>(pm, Wpre, nullptr, pp1, N, 64, 64);
    gemm256<<<dim3(1, mBlocks), 256>>>(pm, Wpre + 64 * 64, nullptr, pp2, N, 64, 64);
    node_edge_reduce<<<(N + 7) / 8, 256>>>(edge_index, edge_attr, bpre, N, E);
    gemm_post<<<mBlocks, 256>>>(Wpost, bpost, N);
    gemm256<<<dim3(3, mBlocks), 256>>>(pon, Wih, bih, pgi, N, 192, 64);
    gemm256<<<dim3(3, mBlocks), 256>>>(x, Whh, bhh, pgh, N, 192, 64);
    gru_kernel<<<(nodeElems + 255) / 256, 256>>>(x, (float*)d_out, N);
}

// round 7
// speedup vs baseline: 2.7890x; 1.0249x over previous
#include <cuda_runtime.h>
#include <math.h>
#include <stdint.h>

#define NN 50000
#define EE 800000
#define CC 64

typedef unsigned long long ull;

// ---------------- scratch ----------------
__device__ float g_m[NN * CC];          // x @ W
__device__ float g_p1[NN * CC];         // m @ Wpre[0:64]   (dst term)
__device__ float g_p2[NN * CC];         // m @ Wpre[64:128] (src term)
__device__ float g_C3[3 * CC];          // We @ Wpre[128:192]
__device__ float g_c3[CC];              // be @ Wpre[128:192]
__device__ int   g_cnt_i[NN];
__device__ int   g_off[NN + 1];
__device__ int   g_cur[NN];
__device__ int   g_eid[EE];
__device__ float g_agg[NN * 4 * CC];    // [mean | min | max | std]
__device__ float g_a[NN];
__device__ float g_ia[NN];
__device__ float g_out_node[NN * CC];
__device__ float g_gi[NN * 3 * CC];
__device__ float g_gh[NN * 3 * CC];
__device__ float g_avgsum[1];

// ---------------- packed f32x2 helpers ----------------
__device__ __forceinline__ ull pack2(float lo, float hi) {
    ull r;
    asm("mov.b64 %0, {%1, %2};" : "=l"(r) : "f"(lo), "f"(hi));
    return r;
}
__device__ __forceinline__ void unpack2(ull v, float& lo, float& hi) {
    asm("mov.b64 {%0, %1}, %2;" : "=f"(lo), "=f"(hi) : "l"(v));
}
__device__ __forceinline__ void fma2(ull& d, ull a, ull b) {
    asm("fma.rn.f32x2 %0, %1, %2, %0;" : "+l"(d) : "l"(a), "l"(b));
}

// ---------------- init ----------------
__global__ void init_kernel(int N) {
    int idx = blockIdx.x * 256 + threadIdx.x;
    if (idx < N) g_cnt_i[idx] = 0;
    if (idx == 0) g_avgsum[0] = 0.f;
}

// ---------------- avg_log ----------------
__global__ void avglog_kernel(const float* __restrict__ deg_hist, int N) {
    int idx = blockIdx.x * 256 + threadIdx.x;
    float v = (idx < N) ? logf(deg_hist[idx] + 1.f) : 0.f;
    #pragma unroll
    for (int o = 16; o; o >>= 1) v += __shfl_down_sync(0xFFFFFFFFu, v, o);
    __shared__ float sred[8];
    if ((threadIdx.x & 31) == 0) sred[threadIdx.x >> 5] = v;
    __syncthreads();
    if (threadIdx.x < 8) {
        v = sred[threadIdx.x];
        #pragma unroll
        for (int o = 4; o; o >>= 1) v += __shfl_down_sync(0xFFu, v, o);
        if (threadIdx.x == 0) atomicAdd(&g_avgsum[0], v);
    }
}

// ---------------- CSR build ----------------
__global__ void count_kernel(const int* __restrict__ edge_index, int E) {
    int idx = blockIdx.x * 256 + threadIdx.x;
    if (idx < E) atomicAdd(&g_cnt_i[edge_index[E + idx]], 1);
}

__global__ void __launch_bounds__(1024) scan_kernel(int N, int E) {
    __shared__ int sh[1024];
    int tid = threadIdx.x;
    int per = (N + 1023) / 1024;
    int start = tid * per;
    int end = start + per; if (end > N) end = N;
    int s = 0;
    for (int i = start; i < end; i++) s += g_cnt_i[i];
    sh[tid] = s;
    __syncthreads();
    for (int d = 1; d < 1024; d <<= 1) {
        int v = (tid >= d) ? sh[tid - d] : 0;
        __syncthreads();
        sh[tid] += v;
        __syncthreads();
    }
    int running = sh[tid] - s;
    for (int i = start; i < end; i++) {
        g_off[i] = running;
        g_cur[i] = running;
        running += g_cnt_i[i];
    }
    if (tid == 1023) g_off[N] = E;
}

__global__ void scatter_kernel(const int* __restrict__ edge_index, int E) {
    int idx = blockIdx.x * 256 + threadIdx.x;
    if (idx < E) {
        int d = edge_index[E + idx];
        int pos = atomicAdd(&g_cur[d], 1);
        g_eid[pos] = idx;
    }
}

// ---------------- prep: C3 = We @ Wpre3, c3 = be @ Wpre3 (256 parallel outputs) ----------------
__global__ void prep_kernel(const float* __restrict__ We, const float* __restrict__ be,
                            const float* __restrict__ Wpre) {
    int t = threadIdx.x;       // 0..255
    int r = t >> 6;            // 0..2 -> C3 rows, 3 -> c3
    int c = t & 63;
    const float* W3 = Wpre + 128 * 64;
    const float* vsrc = (r < 3) ? (We + r * 64) : be;
    float s = 0.f;
    #pragma unroll 8
    for (int j = 0; j < 64; j++) s += vsrc[j] * W3[j * 64 + c];
    if (r < 3) g_C3[r * 64 + c] = s;
    else       g_c3[c] = s;
}

// ---------------- double-buffered SGEMM: BM=128, BN=64, BK=16, 256 threads ----------------
// Micro-tile 4(m)x8(n), FFMA2 packed along n, B pre-packed as u64 pairs (warp-uniform).
__global__ void __launch_bounds__(256) gemm256(const float* __restrict__ A,
                                               const float* __restrict__ B,
                                               const float* __restrict__ bias,
                                               float* __restrict__ Cout,
                                               int M, int Ncol, int K) {
    __shared__ float As[2][16][128];
    __shared__ ull   Bs[2][16][32];
    int tid = threadIdx.x;
    int lane = tid & 31;
    int cg = tid >> 5;
    int mBase = blockIdx.y * 128;
    int nBase = blockIdx.x * 64;
    ull acc[4][4];
    #pragma unroll
    for (int e = 0; e < 4; e++)
        #pragma unroll
        for (int j = 0; j < 4; j++) acc[e][j] = 0ull;

    int ar = tid & 127;
    int ak = (tid >> 7) * 8;
    int brow = tid / 16;
    int bp_idx = (tid % 16) * 2;            // pair index in Bs row
    int bcol = (tid % 16) * 4;              // float col in B
    int m = mBase + ar;

    // prologue: load + stage tile 0
    float4 a0 = make_float4(0.f, 0.f, 0.f, 0.f), a1 = a0;
    if (m < M) {
        const float* ap = &A[(size_t)m * K + ak];
        a0 = *reinterpret_cast<const float4*>(ap);
        a1 = *reinterpret_cast<const float4*>(ap + 4);
    }
    float4 bv = *reinterpret_cast<const float4*>(&B[(size_t)brow * Ncol + nBase + bcol]);

    int nk = K / 16;
    #pragma unroll 1
    for (int it = 0; it < nk; it++) {
        int buf = it & 1;
        // stage current regs
        As[buf][ak + 0][ar] = a0.x; As[buf][ak + 1][ar] = a0.y;
        As[buf][ak + 2][ar] = a0.z; As[buf][ak + 3][ar] = a0.w;
        As[buf][ak + 4][ar] = a1.x; As[buf][ak + 5][ar] = a1.y;
        As[buf][ak + 6][ar] = a1.z; As[buf][ak + 7][ar] = a1.w;
        Bs[buf][brow][bp_idx]     = pack2(bv.x, bv.y);
        Bs[buf][brow][bp_idx + 1] = pack2(bv.z, bv.w);
        __syncthreads();
        // prefetch next tile
        if (it + 1 < nk) {
            int k0 = (it + 1) * 16;
            a0 = make_float4(0.f, 0.f, 0.f, 0.f); a1 = a0;
            if (m < M) {
                const float* ap = &A[(size_t)m * K + k0 + ak];
                a0 = *reinterpret_cast<const float4*>(ap);
                a1 = *reinterpret_cast<const float4*>(ap + 4);
            }
            bv = *reinterpret_cast<const float4*>(&B[(size_t)(k0 + brow) * Ncol + nBase + bcol]);
        }
        // compute
        #pragma unroll
        for (int k = 0; k < 16; k++) {
            float4 a = *reinterpret_cast<const float4*>(&As[buf][k][lane * 4]);
            longlong2 b01 = *reinterpret_cast<const longlong2*>(&Bs[buf][k][cg * 4]);
            longlong2 b23 = *reinterpret_cast<const longlong2*>(&Bs[buf][k][cg * 4 + 2]);
            ull bp[4] = {(ull)b01.x, (ull)b01.y, (ull)b23.x, (ull)b23.y};
            ull ad[4] = {pack2(a.x, a.x), pack2(a.y, a.y), pack2(a.z, a.z), pack2(a.w, a.w)};
            #pragma unroll
            for (int e = 0; e < 4; e++)
                #pragma unroll
                for (int j = 0; j < 4; j++) fma2(acc[e][j], ad[e], bp[j]);
        }
        __syncthreads();
    }

    float bs[8] = {0, 0, 0, 0, 0, 0, 0, 0};
    if (bias) {
        float4 t0 = *reinterpret_cast<const float4*>(&bias[nBase + cg * 8]);
        float4 t1 = *reinterpret_cast<const float4*>(&bias[nBase + cg * 8 + 4]);
        bs[0] = t0.x; bs[1] = t0.y; bs[2] = t0.z; bs[3] = t0.w;
        bs[4] = t1.x; bs[5] = t1.y; bs[6] = t1.z; bs[7] = t1.w;
    }
    #pragma unroll
    for (int e = 0; e < 4; e++) {
        int mm = mBase + lane * 4 + e;
        if (mm < M) {
            float v[8];
            #pragma unroll
            for (int j = 0; j < 4; j++) unpack2(acc[e][j], v[2 * j], v[2 * j + 1]);
            float* cp = &Cout[(size_t)mm * Ncol + nBase + cg * 8];
            *reinterpret_cast<float4*>(cp) =
                make_float4(v[0] + bs[0], v[1] + bs[1], v[2] + bs[2], v[3] + bs[3]);
            *reinterpret_cast<float4*>(cp + 4) =
                make_float4(v[4] + bs[4], v[5] + bs[5], v[6] + bs[6], v[7] + bs[7]);
        }
    }
}

// ---------------- fused edge compute + node reduce (warp per node) ----------------
__global__ void __launch_bounds__(256) node_edge_reduce(const int* __restrict__ edge_index,
                                                        const float* __restrict__ edge_attr,
                                                        const float* __restrict__ bpre,
                                                        int N, int E) {
    int lane = threadIdx.x & 31;
    int n = blockIdx.x * 8 + (threadIdx.x >> 5);
    if (n >= N) return;
    int off0 = g_off[n], off1 = g_off[n + 1];
    int deg = off1 - off0;

    float basea = g_p1[(size_t)n * 64 + lane] + g_c3[lane];
    float baseb = g_p1[(size_t)n * 64 + lane + 32] + g_c3[lane + 32];
    float c30a = g_C3[lane],        c30b = g_C3[lane + 32];
    float c31a = g_C3[64 + lane],   c31b = g_C3[64 + lane + 32];
    float c32a = g_C3[128 + lane],  c32b = g_C3[128 + lane + 32];
    float bpa = bpre[lane], bpb = bpre[lane + 32];

    float s1a = 0.f, s2a = 0.f, s1b = 0.f, s2b = 0.f;
    float mna = 3.4e38f, mxa = -3.4e38f, mnb = 3.4e38f, mxb = -3.4e38f;

    int src_n = 0;
    float4 at_n = make_float4(0.f, 0.f, 0.f, 0.f);
    if (deg > 0) {
        int eid = g_eid[off0];
        src_n = edge_index[eid];
        at_n = *reinterpret_cast<const float4*>(&edge_attr[(size_t)eid * 4]);
    }
    for (int i = off0; i < off1; i++) {
        int src = src_n;
        float4 at = at_n;
        const float* p2 = &g_p2[(size_t)src * 64];
        float va = p2[lane];
        float vb = p2[lane + 32];
        if (i + 1 < off1) {
            int eid = g_eid[i + 1];
            src_n = edge_index[eid];
            at_n = *reinterpret_cast<const float4*>(&edge_attr[(size_t)eid * 4]);
        }
        float ew = at.w;
        float ha = ew * (basea + va + at.x * c30a + at.y * c31a + at.z * c32a) + bpa;
        float hb = ew * (baseb + vb + at.x * c30b + at.y * c31b + at.z * c32b) + bpb;
        s1a += ha; s2a += ha * ha;
        mna = fminf(mna, ha); mxa = fmaxf(mxa, ha);
        s1b += hb; s2b += hb * hb;
        mnb = fminf(mnb, hb); mxb = fmaxf(mxb, hb);
    }

    float cnt = (float)deg;
    float safe = fmaxf(cnt, 1.f);
    float inv = 1.f / safe;
    float meana = s1a * inv, meanb = s1b * inv;
    float stda = sqrtf(fmaxf(s2a * inv - meana * meana, 0.f) + 1e-5f);
    float stdb = sqrtf(fmaxf(s2b * inv - meanb * meanb, 0.f) + 1e-5f);
    if (deg == 0) { mna = 0.f; mxa = 0.f; mnb = 0.f; mxb = 0.f; }
    size_t b = (size_t)n * 256;
    g_agg[b + lane]            = meana;
    g_agg[b + lane + 32]       = meanb;
    g_agg[b + 64 + lane]       = mna;
    g_agg[b + 64 + lane + 32]  = mnb;
    g_agg[b + 128 + lane]      = mxa;
    g_agg[b + 128 + lane + 32] = mxb;
    g_agg[b + 192 + lane]      = stda;
    g_agg[b + 192 + lane + 32] = stdb;
    if (lane == 0) {
        float avg = g_avgsum[0] / (float)N;
        float logd = logf(safe + 1.f);
        float a = logd / avg;
        g_a[n]  = a;
        g_ia[n] = a * (avg / logd);   // fp-composed o3 scale
    }
}

// ---------------- Wpost GEMM (K=832), on-the-fly z, double-buffered ----------------
__global__ void __launch_bounds__(256) gemm_post(const float* __restrict__ Wpost,
                                                 const float* __restrict__ bpost, int M) {
    __shared__ float As[2][16][128];
    __shared__ ull   Bs[2][16][32];
    int tid = threadIdx.x;
    int lane = tid & 31;
    int cg = tid >> 5;
    int mBase = blockIdx.x * 128;
    ull acc[4][4];
    #pragma unroll
    for (int e = 0; e < 4; e++)
        #pragma unroll
        for (int j = 0; j < 4; j++) acc[e][j] = 0ull;

    int ar = tid & 127;
    int ak = (tid >> 7) * 8;
    int brow = tid / 16;
    int bp_idx = (tid % 16) * 2;
    int bcol = (tid % 16) * 4;
    int m = mBase + ar;
    float sa = 0.f, sia = 0.f;
    if (m < M) { sa = g_a[m]; sia = g_ia[m]; }

    // z-row loader into two float4s (k = k0+ak .. +7)
    float4 a0 = make_float4(0.f, 0.f, 0.f, 0.f), a1 = a0;
    {
        if (m < M) {
            #pragma unroll
            for (int q = 0; q < 2; q++) {
                int k = ak + q * 4;
                float sc = 1.f;
                const float* src;
                if (k < 64)       src = &g_m[(size_t)m * 64 + k];
                else if (k < 320) src = &g_agg[(size_t)m * 256 + (k - 64)];
                else if (k < 576) { src = &g_agg[(size_t)m * 256 + (k - 320)]; sc = sa; }
                else              { src = &g_agg[(size_t)m * 256 + (k - 576)]; sc = sia; }
                float4 av = *reinterpret_cast<const float4*>(src);
                av.x *= sc; av.y *= sc; av.z *= sc; av.w *= sc;
                if (q == 0) a0 = av; else a1 = av;
            }
        }
    }
    float4 bv = *reinterpret_cast<const float4*>(&Wpost[(size_t)brow * 64 + bcol]);

    const int nk = 832 / 16;
    #pragma unroll 1
    for (int it = 0; it < nk; it++) {
        int buf = it & 1;
        As[buf][ak + 0][ar] = a0.x; As[buf][ak + 1][ar] = a0.y;
        As[buf][ak + 2][ar] = a0.z; As[buf][ak + 3][ar] = a0.w;
        As[buf][ak + 4][ar] = a1.x; As[buf][ak + 5][ar] = a1.y;
        As[buf][ak + 6][ar] = a1.z; As[buf][ak + 7][ar] = a1.w;
        Bs[buf][brow][bp_idx]     = pack2(bv.x, bv.y);
        Bs[buf][brow][bp_idx + 1] = pack2(bv.z, bv.w);
        __syncthreads();
        if (it + 1 < nk) {
            int k0 = (it + 1) * 16;
            a0 = make_float4(0.f, 0.f, 0.f, 0.f); a1 = a0;
            if (m < M) {
                #pragma unroll
                for (int q = 0; q < 2; q++) {
                    int k = k0 + ak + q * 4;
                    float sc = 1.f;
                    const float* src;
                    if (k < 64)       src = &g_m[(size_t)m * 64 + k];
                    else if (k < 320) src = &g_agg[(size_t)m * 256 + (k - 64)];
                    else if (k < 576) { src = &g_agg[(size_t)m * 256 + (k - 320)]; sc = sa; }
                    else              { src = &g_agg[(size_t)m * 256 + (k - 576)]; sc = sia; }
                    float4 av = *reinterpret_cast<const float4*>(src);
                    av.x *= sc; av.y *= sc; av.z *= sc; av.w *= sc;
                    if (q == 0) a0 = av; else a1 = av;
                }
            }
            bv = *reinterpret_cast<const float4*>(&Wpost[(size_t)(k0 + brow) * 64 + bcol]);
        }
        #pragma unroll
        for (int k = 0; k < 16; k++) {
            float4 a = *reinterpret_cast<const float4*>(&As[buf][k][lane * 4]);
            longlong2 b01 = *reinterpret_cast<const longlong2*>(&Bs[buf][k][cg * 4]);
            longlong2 b23 = *reinterpret_cast<const longlong2*>(&Bs[buf][k][cg * 4 + 2]);
            ull bp[4] = {(ull)b01.x, (ull)b01.y, (ull)b23.x, (ull)b23.y};
            ull ad[4] = {pack2(a.x, a.x), pack2(a.y, a.y), pack2(a.z, a.z), pack2(a.w, a.w)};
            #pragma unroll
            for (int e = 0; e < 4; e++)
                #pragma unroll
                for (int j = 0; j < 4; j++) fma2(acc[e][j], ad[e], bp[j]);
        }
        __syncthreads();
    }

    float4 t0 = *reinterpret_cast<const float4*>(&bpost[cg * 8]);
    float4 t1 = *reinterpret_cast<const float4*>(&bpost[cg * 8 + 4]);
    float bs[8] = {t0.x, t0.y, t0.z, t0.w, t1.x, t1.y, t1.z, t1.w};
    #pragma unroll
    for (int e = 0; e < 4; e++) {
        int mm = mBase + lane * 4 + e;
        if (mm < M) {
            float v[8];
            #pragma unroll
            for (int j = 0; j < 4; j++) unpack2(acc[e][j], v[2 * j], v[2 * j + 1]);
            float* cp = &g_out_node[(size_t)mm * 64 + cg * 8];
            *reinterpret_cast<float4*>(cp) =
                make_float4(v[0] + bs[0], v[1] + bs[1], v[2] + bs[2], v[3] + bs[3]);
            *reinterpret_cast<float4*>(cp + 4) =
                make_float4(v[4] + bs[4], v[5] + bs[5], v[6] + bs[6], v[7] + bs[7]);
        }
    }
}

// ---------------- GRU elementwise ----------------
__global__ void gru_kernel(const float* __restrict__ x, float* __restrict__ out, int N) {
    int idx = blockIdx.x * 256 + threadIdx.x;
    if (idx >= N * CC) return;
    int n = idx >> 6, c = idx & 63;
    size_t b = (size_t)n * 192;
    float ir = g_gi[b + c],        hr = g_gh[b + c];
    float iz = g_gi[b + 64 + c],   hz = g_gh[b + 64 + c];
    float in_ = g_gi[b + 128 + c], hn = g_gh[b + 128 + c];
    float r = 1.f / (1.f + expf(-(ir + hr)));
    float z = 1.f / (1.f + expf(-(iz + hz)));
    float nn = tanhf(in_ + r * hn);
    out[idx] = (1.f - z) * nn + z * x[idx];
}

// ---------------- launch ----------------
extern "C" void kernel_launch(void* const* d_in, const int* in_sizes, int n_in,
                              void* d_out, int out_size) {
    const float* x         = (const float*)d_in[0];
    const float* edge_attr = (const float*)d_in[1];
    const float* deg_hist  = (const float*)d_in[2];
    const float* W         = (const float*)d_in[3];
    const float* We        = (const float*)d_in[4];
    const float* be        = (const float*)d_in[5];
    const float* Wpre      = (const float*)d_in[6];
    const float* bpre      = (const float*)d_in[7];
    const float* Wpost     = (const float*)d_in[8];
    const float* bpost     = (const float*)d_in[9];
    const float* Wih       = (const float*)d_in[10];
    const float* bih       = (const float*)d_in[11];
    const float* Whh       = (const float*)d_in[12];
    const float* bhh       = (const float*)d_in[13];
    const int*   edge_index = (const int*)d_in[14];

    int N = in_sizes[0] / CC;
    int E = in_sizes[14] / 2;

    float *pm, *pp1, *pp2, *pon, *pgi, *pgh;
    cudaGetSymbolAddress((void**)&pm,  g_m);
    cudaGetSymbolAddress((void**)&pp1, g_p1);
    cudaGetSymbolAddress((void**)&pp2, g_p2);
    cudaGetSymbolAddress((void**)&pon, g_out_node);
    cudaGetSymbolAddress((void**)&pgi, g_gi);
    cudaGetSymbolAddress((void**)&pgh, g_gh);

    int nodeElems = N * CC;
    int mBlocks = (N + 127) / 128;
    int eBlocks256 = (E + 255) / 256;

    init_kernel<<<(N + 255) / 256, 256>>>(N);
    avglog_kernel<<<(N + 255) / 256, 256>>>(deg_hist, N);
    count_kernel<<<eBlocks256, 256>>>(edge_index, E);
    prep_kernel<<<1, 256>>>(We, be, Wpre);
    gemm256<<<dim3(1, mBlocks), 256>>>(x, W, nullptr, pm, N, 64, 64);
    scan_kernel<<<1, 1024>>>(N, E);
    scatter_kernel<<<eBlocks256, 256>>>(edge_index, E);
    gemm256<<<dim3(1, mBlocks), 256>>>(pm, Wpre, nullptr, pp1, N, 64, 64);
    gemm256<<<dim3(1, mBlocks), 256>>>(pm, Wpre + 64 * 64, nullptr, pp2, N, 64, 64);
    node_edge_reduce<<<(N + 7) / 8, 256>>>(edge_index, edge_attr, bpre, N, E);
    gemm_post<<<mBlocks, 256>>>(Wpost, bpost, N);
    gemm256<<<dim3(3, mBlocks), 256>>>(pon, Wih, bih, pgi, N, 192, 64);
    gemm256<<<dim3(3, mBlocks), 256>>>(x, Whh, bhh, pgh, N, 192, 64);
    gru_kernel<<<(nodeElems + 255) / 256, 256>>>(x, (float*)d_out, N);
}